// round 1
// baseline (speedup 1.0000x reference)
#include <cuda_runtime.h>
#include <cstdint>

// Problem constants (fixed shapes)
#define BATCH 4
#define SEQ   1024
#define CH    1024
#define HEADS 16
#define DH    64
#define TOKENS (BATCH * SEQ)          // 4096
#define BH (BATCH * HEADS)            // 64
#define OUT_ELEMS (TOKENS * CH)       // 4194304

#define ENTMAX_ITERS 30
#define SCALE 0.0625f                 // (1/sqrt(64)) * (alpha-1) = 1/8 * 0.5

// Scratch (static device arrays; no allocation)
__device__ float g_q[BH * SEQ * DH];
__device__ float g_k[BH * SEQ * DH];
__device__ float g_v[BH * SEQ * DH];
__device__ float g_ctx[TOKENS * CH];

// ---------------------------------------------------------------------------
// GEMM: out = A[M x 1024] @ W[1024 x 1024] + bias
// BM=128, BN=64, BK=16, 256 threads, 8x4 microtile, reg-staged double buffer.
// src_mode: 0 -> A param, 1 -> g_ctx
// dst_mode: 0/1/2 -> g_q/g_k/g_v (head-reordered), 3 -> plain to out param
// ---------------------------------------------------------------------------
__global__ __launch_bounds__(256) void gemm_xw(
    const float* __restrict__ Ain, const float* __restrict__ W,
    const float* __restrict__ bias, float* __restrict__ outp,
    int src_mode, int dst_mode)
{
    __shared__ float As[16][132];  // transposed: As[k][m], padded
    __shared__ float Bs[16][68];

    const float* A = (src_mode == 0) ? Ain : g_ctx;

    int tid = threadIdx.x;
    int tx = tid & 15;         // n direction, 16 * 4 = 64
    int ty = tid >> 4;         // m direction, 16 * 8 = 128
    int n0 = blockIdx.x * 64;
    int m0 = blockIdx.y * 128;

    // A tile: 128 rows x 16 k = 512 float4, 2 per thread
    int a_row0 = (tid) >> 2;             // 0..63
    int a_c4_0 = (tid) & 3;
    int a_row1 = (tid + 256) >> 2;       // 64..127
    int a_c4_1 = (tid + 256) & 3;
    // B tile: 16 rows x 64 = 256 float4, 1 per thread
    int b_row = tid >> 4;                // 0..15
    int b_c4  = tid & 15;

    float4 ra0, ra1, rb;
    {
        int kc = 0;
        ra0 = *(const float4*)(A + (size_t)(m0 + a_row0) * 1024 + kc + a_c4_0 * 4);
        ra1 = *(const float4*)(A + (size_t)(m0 + a_row1) * 1024 + kc + a_c4_1 * 4);
        rb  = *(const float4*)(W + (size_t)(kc + b_row) * 1024 + n0 + b_c4 * 4);
    }

    float acc[8][4];
#pragma unroll
    for (int i = 0; i < 8; i++)
#pragma unroll
        for (int j = 0; j < 4; j++) acc[i][j] = 0.0f;

    for (int kc = 0; kc < 1024; kc += 16) {
        // store staged regs to smem
        As[a_c4_0 * 4 + 0][a_row0] = ra0.x;
        As[a_c4_0 * 4 + 1][a_row0] = ra0.y;
        As[a_c4_0 * 4 + 2][a_row0] = ra0.z;
        As[a_c4_0 * 4 + 3][a_row0] = ra0.w;
        As[a_c4_1 * 4 + 0][a_row1] = ra1.x;
        As[a_c4_1 * 4 + 1][a_row1] = ra1.y;
        As[a_c4_1 * 4 + 2][a_row1] = ra1.z;
        As[a_c4_1 * 4 + 3][a_row1] = ra1.w;
        *(float4*)&Bs[b_row][b_c4 * 4] = rb;
        __syncthreads();

        if (kc + 16 < 1024) {
            int kn = kc + 16;
            ra0 = *(const float4*)(A + (size_t)(m0 + a_row0) * 1024 + kn + a_c4_0 * 4);
            ra1 = *(const float4*)(A + (size_t)(m0 + a_row1) * 1024 + kn + a_c4_1 * 4);
            rb  = *(const float4*)(W + (size_t)(kn + b_row) * 1024 + n0 + b_c4 * 4);
        }

#pragma unroll
        for (int k = 0; k < 16; k++) {
            float4 va0 = *(const float4*)&As[k][ty * 8];
            float4 va1 = *(const float4*)&As[k][ty * 8 + 4];
            float4 vb  = *(const float4*)&Bs[k][tx * 4];
            float a[8] = {va0.x, va0.y, va0.z, va0.w, va1.x, va1.y, va1.z, va1.w};
            float b[4] = {vb.x, vb.y, vb.z, vb.w};
#pragma unroll
            for (int i = 0; i < 8; i++)
#pragma unroll
                for (int j = 0; j < 4; j++)
                    acc[i][j] = fmaf(a[i], b[j], acc[i][j]);
        }
        __syncthreads();
    }

    // epilogue
    float bv[4];
#pragma unroll
    for (int j = 0; j < 4; j++) bv[j] = bias[n0 + tx * 4 + j];

    float* dst;
    if (dst_mode == 0) dst = g_q;
    else if (dst_mode == 1) dst = g_k;
    else if (dst_mode == 2) dst = g_v;
    else dst = outp;

#pragma unroll
    for (int i = 0; i < 8; i++) {
        int token = m0 + ty * 8 + i;
#pragma unroll
        for (int j = 0; j < 4; j++) {
            float val = acc[i][j] + bv[j];
            int ng = n0 + tx * 4 + j;
            if (dst_mode <= 2) {
                int h = ng >> 6, dh = ng & 63;
                int bidx = token >> 10, ntok = token & 1023;
                dst[(((size_t)(bidx * HEADS + h)) * SEQ + ntok) * DH + dh] = val;
            } else {
                dst[(size_t)token * CH + ng] = val;
            }
        }
    }
}

// ---------------------------------------------------------------------------
// Fused scores + entmax-1.5 bisection. Block: 512 threads = 16 warps,
// 2 query rows per warp (32 rows/block). Scores live in registers
// (32 per lane per row). K streamed through smem in 64-row chunks.
// ---------------------------------------------------------------------------
__global__ __launch_bounds__(512) void attn_entmax(float* __restrict__ attn)
{
    __shared__ float Qs[32][68];
    __shared__ float Ks[64][68];

    int tid = threadIdx.x;
    int w = tid >> 5;
    int l = tid & 31;
    int bh = blockIdx.y;
    int rowbase = blockIdx.x * 32;
    int r0 = w * 2;

    const float* qbase = g_q + ((size_t)bh * SEQ + rowbase) * DH;
    const float* kbase = g_k + (size_t)bh * SEQ * DH;

    // load Q tile: 32 rows x 64 = 512 float4 (one per thread)
    {
        int row = tid >> 4, c4 = tid & 15;
        float4 v = *(const float4*)(qbase + (size_t)row * DH + c4 * 4);
        *(float4*)&Qs[row][c4 * 4] = v;
    }

    // K chunk staging indices: 64 rows x 16 f4 = 1024 f4, 2 per thread
    int k_row0 = tid >> 4;          // 0..31
    int k_row1 = k_row0 + 32;       // 32..63
    int k_c4 = (tid & 15) * 4;

    float4 rk0, rk1;
    rk0 = *(const float4*)(kbase + (size_t)k_row0 * DH + k_c4);
    rk1 = *(const float4*)(kbase + (size_t)k_row1 * DH + k_c4);

    float s0[32], s1[32];

    __syncthreads();  // Qs visible

#pragma unroll
    for (int c = 0; c < 16; c++) {
        *(float4*)&Ks[k_row0][k_c4] = rk0;
        *(float4*)&Ks[k_row1][k_c4] = rk1;
        __syncthreads();

        if (c < 15) {
            const float* kn = kbase + (size_t)(c + 1) * 64 * DH;
            rk0 = *(const float4*)(kn + (size_t)k_row0 * DH + k_c4);
            rk1 = *(const float4*)(kn + (size_t)k_row1 * DH + k_c4);
        }

        float a00 = 0.f, a01 = 0.f, a10 = 0.f, a11 = 0.f;
#pragma unroll
        for (int d4 = 0; d4 < 16; d4++) {
            float4 k0 = *(const float4*)&Ks[l][d4 * 4];
            float4 k1 = *(const float4*)&Ks[l + 32][d4 * 4];
            float4 q0 = *(const float4*)&Qs[r0][d4 * 4];
            float4 q1 = *(const float4*)&Qs[r0 + 1][d4 * 4];
            a00 = fmaf(q0.x, k0.x, a00); a00 = fmaf(q0.y, k0.y, a00);
            a00 = fmaf(q0.z, k0.z, a00); a00 = fmaf(q0.w, k0.w, a00);
            a01 = fmaf(q0.x, k1.x, a01); a01 = fmaf(q0.y, k1.y, a01);
            a01 = fmaf(q0.z, k1.z, a01); a01 = fmaf(q0.w, k1.w, a01);
            a10 = fmaf(q1.x, k0.x, a10); a10 = fmaf(q1.y, k0.y, a10);
            a10 = fmaf(q1.z, k0.z, a10); a10 = fmaf(q1.w, k0.w, a10);
            a11 = fmaf(q1.x, k1.x, a11); a11 = fmaf(q1.y, k1.y, a11);
            a11 = fmaf(q1.z, k1.z, a11); a11 = fmaf(q1.w, k1.w, a11);
        }
        s0[2 * c] = a00; s0[2 * c + 1] = a01;
        s1[2 * c] = a10; s1[2 * c + 1] = a11;
        __syncthreads();
    }

    // ---- entmax-1.5 bisection on the two rows (Xa = scores * (alpha-1)) ----
#pragma unroll
    for (int j = 0; j < 32; j++) { s0[j] *= SCALE; s1[j] *= SCALE; }

    // row max
    float mx0 = s0[0], mx1 = s1[0];
#pragma unroll
    for (int j = 1; j < 32; j++) { mx0 = fmaxf(mx0, s0[j]); mx1 = fmaxf(mx1, s1[j]); }
#pragma unroll
    for (int o = 16; o > 0; o >>= 1) {
        mx0 = fmaxf(mx0, __shfl_xor_sync(0xffffffffu, mx0, o));
        mx1 = fmaxf(mx1, __shfl_xor_sync(0xffffffffu, mx1, o));
    }

    float tlo0 = mx0 - 1.0f, tlo1 = mx1 - 1.0f;
    float dm0 = (mx0 - 0.03125f) - tlo0;   // tau_hi - tau_lo, (1/1024)^0.5 = 1/32
    float dm1 = (mx1 - 0.03125f) - tlo1;

    // f_lo
    float fl0 = 0.f, fl1 = 0.f;
#pragma unroll
    for (int j = 0; j < 32; j++) {
        float t = fmaxf(s0[j] - tlo0, 0.f); fl0 = fmaf(t, t, fl0);
        t = fmaxf(s1[j] - tlo1, 0.f);       fl1 = fmaf(t, t, fl1);
    }
#pragma unroll
    for (int o = 16; o > 0; o >>= 1) {
        fl0 += __shfl_xor_sync(0xffffffffu, fl0, o);
        fl1 += __shfl_xor_sync(0xffffffffu, fl1, o);
    }
    fl0 -= 1.0f; fl1 -= 1.0f;

    float tm0 = tlo0, tm1 = tlo1;
#pragma unroll 1
    for (int it = 0; it < ENTMAX_ITERS; it++) {
        dm0 *= 0.5f; dm1 *= 0.5f;
        tm0 = tlo0 + dm0; tm1 = tlo1 + dm1;
        float c0 = 0.f, c1 = 0.f;
#pragma unroll
        for (int j = 0; j < 32; j++) {
            float t = fmaxf(s0[j] - tm0, 0.f); c0 = fmaf(t, t, c0);
            t = fmaxf(s1[j] - tm1, 0.f);       c1 = fmaf(t, t, c1);
        }
#pragma unroll
        for (int o = 16; o > 0; o >>= 1) {
            c0 += __shfl_xor_sync(0xffffffffu, c0, o);
            c1 += __shfl_xor_sync(0xffffffffu, c1, o);
        }
        float fm0 = c0 - 1.0f, fm1 = c1 - 1.0f;
        if (fm0 * fl0 >= 0.f) tlo0 = tm0;
        if (fm1 * fl1 >= 0.f) tlo1 = tm1;
    }

    // final p with last tau_m, normalize
    float su0 = 0.f, su1 = 0.f;
#pragma unroll
    for (int j = 0; j < 32; j++) {
        float t = fmaxf(s0[j] - tm0, 0.f); s0[j] = t * t; su0 += s0[j];
        t = fmaxf(s1[j] - tm1, 0.f);       s1[j] = t * t; su1 += s1[j];
    }
#pragma unroll
    for (int o = 16; o > 0; o >>= 1) {
        su0 += __shfl_xor_sync(0xffffffffu, su0, o);
        su1 += __shfl_xor_sync(0xffffffffu, su1, o);
    }
    float inv0 = 1.0f / su0, inv1 = 1.0f / su1;

    float* ar0 = attn + ((size_t)bh * SEQ + rowbase + r0) * SEQ;
    float* ar1 = ar0 + SEQ;
#pragma unroll
    for (int c = 0; c < 16; c++) {
        ar0[c * 64 + l]      = s0[2 * c] * inv0;
        ar0[c * 64 + 32 + l] = s0[2 * c + 1] * inv0;
        ar1[c * 64 + l]      = s1[2 * c] * inv1;
        ar1[c * 64 + 32 + l] = s1[2 * c + 1] * inv1;
    }
}

// ---------------------------------------------------------------------------
// attn @ V per head: [1024 x 1024] @ [1024 x 64] -> ctx (B,N,C layout)
// BM=128, BN=64 (full), BK=32, 256 threads, 8x4 microtile.
// ---------------------------------------------------------------------------
__global__ __launch_bounds__(256) void gemm_av(const float* __restrict__ attn)
{
    __shared__ float As[32][132];   // transposed [k][m]
    __shared__ float Bs[32][68];

    int tid = threadIdx.x;
    int tx = tid & 15;
    int ty = tid >> 4;
    int m0 = blockIdx.x * 128;
    int bh = blockIdx.y;

    const float* A = attn + (size_t)bh * SEQ * SEQ;
    const float* V = g_v + (size_t)bh * SEQ * DH;

    // A tile: 128 x 32 = 1024 f4, 4 per thread
    int a_row[4], a_c4[4];
#pragma unroll
    for (int i = 0; i < 4; i++) {
        int idx = tid + i * 256;
        a_row[i] = idx >> 3;       // 32 floats = 8 f4 per row
        a_c4[i]  = idx & 7;
    }
    // B tile: 32 x 64 = 512 f4, 2 per thread
    int b_row[2], b_c4[2];
#pragma unroll
    for (int i = 0; i < 2; i++) {
        int idx = tid + i * 256;
        b_row[i] = idx >> 4;
        b_c4[i]  = idx & 15;
    }

    float4 ra[4], rbv[2];
#pragma unroll
    for (int i = 0; i < 4; i++)
        ra[i] = *(const float4*)(A + (size_t)(m0 + a_row[i]) * SEQ + a_c4[i] * 4);
#pragma unroll
    for (int i = 0; i < 2; i++)
        rbv[i] = *(const float4*)(V + (size_t)b_row[i] * DH + b_c4[i] * 4);

    float acc[8][4];
#pragma unroll
    for (int i = 0; i < 8; i++)
#pragma unroll
        for (int j = 0; j < 4; j++) acc[i][j] = 0.0f;

    for (int kc = 0; kc < 1024; kc += 32) {
#pragma unroll
        for (int i = 0; i < 4; i++) {
            As[a_c4[i] * 4 + 0][a_row[i]] = ra[i].x;
            As[a_c4[i] * 4 + 1][a_row[i]] = ra[i].y;
            As[a_c4[i] * 4 + 2][a_row[i]] = ra[i].z;
            As[a_c4[i] * 4 + 3][a_row[i]] = ra[i].w;
        }
#pragma unroll
        for (int i = 0; i < 2; i++)
            *(float4*)&Bs[b_row[i]][b_c4[i] * 4] = rbv[i];
        __syncthreads();

        if (kc + 32 < 1024) {
            int kn = kc + 32;
#pragma unroll
            for (int i = 0; i < 4; i++)
                ra[i] = *(const float4*)(A + (size_t)(m0 + a_row[i]) * SEQ + kn + a_c4[i] * 4);
#pragma unroll
            for (int i = 0; i < 2; i++)
                rbv[i] = *(const float4*)(V + (size_t)(kn + b_row[i]) * DH + b_c4[i] * 4);
        }

#pragma unroll
        for (int k = 0; k < 32; k++) {
            float4 va0 = *(const float4*)&As[k][ty * 8];
            float4 va1 = *(const float4*)&As[k][ty * 8 + 4];
            float4 vb  = *(const float4*)&Bs[k][tx * 4];
            float a[8] = {va0.x, va0.y, va0.z, va0.w, va1.x, va1.y, va1.z, va1.w};
            float b[4] = {vb.x, vb.y, vb.z, vb.w};
#pragma unroll
            for (int i = 0; i < 8; i++)
#pragma unroll
                for (int j = 0; j < 4; j++)
                    acc[i][j] = fmaf(a[i], b[j], acc[i][j]);
        }
        __syncthreads();
    }

    int bidx = bh >> 4, h = bh & 15;
#pragma unroll
    for (int i = 0; i < 8; i++) {
        int m = m0 + ty * 8 + i;
#pragma unroll
        for (int j = 0; j < 4; j++) {
            g_ctx[((size_t)(bidx * SEQ + m)) * CH + h * DH + tx * 4 + j] = acc[i][j];
        }
    }
}

// ---------------------------------------------------------------------------
extern "C" void kernel_launch(void* const* d_in, const int* in_sizes, int n_in,
                              void* d_out, int out_size)
{
    const float* x  = (const float*)d_in[0];
    const float* Wq = (const float*)d_in[1];
    const float* bq = (const float*)d_in[2];
    const float* Wk = (const float*)d_in[3];
    const float* bk = (const float*)d_in[4];
    const float* Wv = (const float*)d_in[5];
    const float* bv = (const float*)d_in[6];
    const float* Wo = (const float*)d_in[7];
    const float* bo = (const float*)d_in[8];

    float* out_ptr  = (float*)d_out;                // [B,N,C]
    float* attn_ptr = out_ptr + OUT_ELEMS;          // [B,H,N,N]

    dim3 gx(16, 32);   // (1024/64, 4096/128)
    // QKV projections
    gemm_xw<<<gx, 256>>>(x, Wq, bq, nullptr, 0, 0);
    gemm_xw<<<gx, 256>>>(x, Wk, bk, nullptr, 0, 1);
    gemm_xw<<<gx, 256>>>(x, Wv, bv, nullptr, 0, 2);

    // scores + entmax -> attn output region
    dim3 ge(32, BH);   // (1024/32 rows, 64 heads)
    attn_entmax<<<ge, 512>>>(attn_ptr);

    // attn @ V -> ctx
    dim3 ga(8, BH);    // (1024/128, 64)
    gemm_av<<<ga, 256>>>(attn_ptr);

    // output projection -> d_out
    gemm_xw<<<gx, 256>>>(nullptr, Wo, bo, out_ptr, 1, 3);
}

// round 2
// speedup vs baseline: 1.0488x; 1.0488x over previous
#include <cuda_runtime.h>
#include <cstdint>

#define BATCH 4
#define SEQ   1024
#define CH    1024
#define HEADS 16
#define DH    64
#define TOKENS (BATCH * SEQ)
#define BH (BATCH * HEADS)
#define OUT_ELEMS (TOKENS * CH)

#define BISECT_ITERS 12
#define SOLVE_ITERS 3
#define SCALE 0.0625f   // (1/sqrt(64)) * (alpha-1)

__device__ float g_q[BH * SEQ * DH];
__device__ float g_k[BH * SEQ * DH];
__device__ float g_v[BH * SEQ * DH];
__device__ float g_ctx[TOKENS * CH];

// ---------------------------------------------------------------------------
// GEMM: out = A[4096 x 1024] @ W[1024 x 1024] + bias
// BM=128, BN=128, BK=16, 256 threads, 8x8 microtile, 2-stage smem + reg stage.
// ---------------------------------------------------------------------------
__global__ __launch_bounds__(256) void gemm_xw(
    const float* __restrict__ Ain, const float* __restrict__ W,
    const float* __restrict__ bias, float* __restrict__ outp,
    int src_mode, int dst_mode)
{
    __shared__ float As[2][16][132];   // [k][m]
    __shared__ float Bs[2][16][132];   // [k][n]

    const float* A = (src_mode == 0) ? Ain : g_ctx;

    int tid = threadIdx.x;
    int tx = tid & 15;          // n: 16 * 8 = 128
    int ty = tid >> 4;          // m: 16 * 8 = 128
    int n0 = blockIdx.x * 128;
    int m0 = blockIdx.y * 128;

    // A tile: 128 rows x 16 = 512 f4 (4 f4 per row), 2 per thread
    int ar[2], ac[2], br[2], bc[2];
#pragma unroll
    for (int i = 0; i < 2; i++) {
        int idx = tid + i * 256;
        ar[i] = idx >> 2;  ac[i] = idx & 3;
        br[i] = idx >> 5;  bc[i] = idx & 31;   // B tile: 16 rows x 128 = 512 f4
    }

    float4 ra[2], rb[2];
#pragma unroll
    for (int i = 0; i < 2; i++) {
        ra[i] = *(const float4*)(A + (size_t)(m0 + ar[i]) * 1024 + ac[i] * 4);
        rb[i] = *(const float4*)(W + (size_t)br[i] * 1024 + n0 + bc[i] * 4);
    }
#pragma unroll
    for (int i = 0; i < 2; i++) {
        As[0][ac[i] * 4 + 0][ar[i]] = ra[i].x;
        As[0][ac[i] * 4 + 1][ar[i]] = ra[i].y;
        As[0][ac[i] * 4 + 2][ar[i]] = ra[i].z;
        As[0][ac[i] * 4 + 3][ar[i]] = ra[i].w;
        *(float4*)&Bs[0][br[i]][bc[i] * 4] = rb[i];
    }
    __syncthreads();

    float acc[8][8];
#pragma unroll
    for (int i = 0; i < 8; i++)
#pragma unroll
        for (int j = 0; j < 8; j++) acc[i][j] = 0.0f;

#pragma unroll 1
    for (int t = 0; t < 64; t++) {
        int buf = t & 1;
        if (t < 63) {
            int kn = (t + 1) * 16;
#pragma unroll
            for (int i = 0; i < 2; i++) {
                ra[i] = *(const float4*)(A + (size_t)(m0 + ar[i]) * 1024 + kn + ac[i] * 4);
                rb[i] = *(const float4*)(W + (size_t)(kn + br[i]) * 1024 + n0 + bc[i] * 4);
            }
        }
#pragma unroll
        for (int k = 0; k < 16; k++) {
            float4 a0 = *(const float4*)&As[buf][k][ty * 8];
            float4 a1 = *(const float4*)&As[buf][k][ty * 8 + 4];
            float4 b0 = *(const float4*)&Bs[buf][k][tx * 8];
            float4 b1 = *(const float4*)&Bs[buf][k][tx * 8 + 4];
            float a[8] = {a0.x, a0.y, a0.z, a0.w, a1.x, a1.y, a1.z, a1.w};
            float b[8] = {b0.x, b0.y, b0.z, b0.w, b1.x, b1.y, b1.z, b1.w};
#pragma unroll
            for (int i = 0; i < 8; i++)
#pragma unroll
                for (int j = 0; j < 8; j++)
                    acc[i][j] = fmaf(a[i], b[j], acc[i][j]);
        }
        if (t < 63) {
            int nb = buf ^ 1;
#pragma unroll
            for (int i = 0; i < 2; i++) {
                As[nb][ac[i] * 4 + 0][ar[i]] = ra[i].x;
                As[nb][ac[i] * 4 + 1][ar[i]] = ra[i].y;
                As[nb][ac[i] * 4 + 2][ar[i]] = ra[i].z;
                As[nb][ac[i] * 4 + 3][ar[i]] = ra[i].w;
                *(float4*)&Bs[nb][br[i]][bc[i] * 4] = rb[i];
            }
            __syncthreads();
        }
    }

    float bv[8];
#pragma unroll
    for (int j = 0; j < 8; j++) bv[j] = bias[n0 + tx * 8 + j];

    int ng0 = n0 + tx * 8;
    if (dst_mode <= 2) {
        float* dst = (dst_mode == 0) ? g_q : (dst_mode == 1) ? g_k : g_v;
        int h = ng0 >> 6, dh = ng0 & 63;   // h constant over this thread's 8 cols
#pragma unroll
        for (int i = 0; i < 8; i++) {
            int token = m0 + ty * 8 + i;
            int bidx = token >> 10, ntok = token & 1023;
            float* p = dst + (((size_t)(bidx * HEADS + h)) * SEQ + ntok) * DH + dh;
            float4 v0 = {acc[i][0] + bv[0], acc[i][1] + bv[1], acc[i][2] + bv[2], acc[i][3] + bv[3]};
            float4 v1 = {acc[i][4] + bv[4], acc[i][5] + bv[5], acc[i][6] + bv[6], acc[i][7] + bv[7]};
            *(float4*)p = v0;
            *(float4*)(p + 4) = v1;
        }
    } else {
#pragma unroll
        for (int i = 0; i < 8; i++) {
            int token = m0 + ty * 8 + i;
            float* p = outp + (size_t)token * CH + ng0;
            float4 v0 = {acc[i][0] + bv[0], acc[i][1] + bv[1], acc[i][2] + bv[2], acc[i][3] + bv[3]};
            float4 v1 = {acc[i][4] + bv[4], acc[i][5] + bv[5], acc[i][6] + bv[6], acc[i][7] + bv[7]};
            *(float4*)p = v0;
            *(float4*)(p + 4) = v1;
        }
    }
}

// ---------------------------------------------------------------------------
// Fused scores + entmax-1.5. 512 thr = 16 warps, 2 rows/warp.
// 12 bisection passes + 3 analytic quadratic-solve passes.
// ---------------------------------------------------------------------------
__global__ __launch_bounds__(512) void attn_entmax(float* __restrict__ attn)
{
    __shared__ float Qs[32][68];
    __shared__ float Ks[64][68];

    int tid = threadIdx.x;
    int w = tid >> 5;
    int l = tid & 31;
    int bh = blockIdx.y;
    int rowbase = blockIdx.x * 32;
    int r0 = w * 2;

    const float* qbase = g_q + ((size_t)bh * SEQ + rowbase) * DH;
    const float* kbase = g_k + (size_t)bh * SEQ * DH;

    {
        int row = tid >> 4, c4 = tid & 15;
        float4 v = *(const float4*)(qbase + (size_t)row * DH + c4 * 4);
        *(float4*)&Qs[row][c4 * 4] = v;
    }

    int k_row0 = tid >> 4;
    int k_row1 = k_row0 + 32;
    int k_c4 = (tid & 15) * 4;

    float4 rk0 = *(const float4*)(kbase + (size_t)k_row0 * DH + k_c4);
    float4 rk1 = *(const float4*)(kbase + (size_t)k_row1 * DH + k_c4);

    float s0[32], s1[32];
    __syncthreads();

#pragma unroll
    for (int c = 0; c < 16; c++) {
        *(float4*)&Ks[k_row0][k_c4] = rk0;
        *(float4*)&Ks[k_row1][k_c4] = rk1;
        __syncthreads();
        if (c < 15) {
            const float* kn = kbase + (size_t)(c + 1) * 64 * DH;
            rk0 = *(const float4*)(kn + (size_t)k_row0 * DH + k_c4);
            rk1 = *(const float4*)(kn + (size_t)k_row1 * DH + k_c4);
        }
        float a00 = 0.f, a01 = 0.f, a10 = 0.f, a11 = 0.f;
#pragma unroll
        for (int d4 = 0; d4 < 16; d4++) {
            float4 k0 = *(const float4*)&Ks[l][d4 * 4];
            float4 k1 = *(const float4*)&Ks[l + 32][d4 * 4];
            float4 q0 = *(const float4*)&Qs[r0][d4 * 4];
            float4 q1 = *(const float4*)&Qs[r0 + 1][d4 * 4];
            a00 = fmaf(q0.x, k0.x, a00); a00 = fmaf(q0.y, k0.y, a00);
            a00 = fmaf(q0.z, k0.z, a00); a00 = fmaf(q0.w, k0.w, a00);
            a01 = fmaf(q0.x, k1.x, a01); a01 = fmaf(q0.y, k1.y, a01);
            a01 = fmaf(q0.z, k1.z, a01); a01 = fmaf(q0.w, k1.w, a01);
            a10 = fmaf(q1.x, k0.x, a10); a10 = fmaf(q1.y, k0.y, a10);
            a10 = fmaf(q1.z, k0.z, a10); a10 = fmaf(q1.w, k0.w, a10);
            a11 = fmaf(q1.x, k1.x, a11); a11 = fmaf(q1.y, k1.y, a11);
            a11 = fmaf(q1.z, k1.z, a11); a11 = fmaf(q1.w, k1.w, a11);
        }
        s0[2 * c] = a00; s0[2 * c + 1] = a01;
        s1[2 * c] = a10; s1[2 * c + 1] = a11;
        __syncthreads();
    }

#pragma unroll
    for (int j = 0; j < 32; j++) { s0[j] *= SCALE; s1[j] *= SCALE; }

    float mx0 = s0[0], mx1 = s1[0];
#pragma unroll
    for (int j = 1; j < 32; j++) { mx0 = fmaxf(mx0, s0[j]); mx1 = fmaxf(mx1, s1[j]); }
#pragma unroll
    for (int o = 16; o > 0; o >>= 1) {
        mx0 = fmaxf(mx0, __shfl_xor_sync(0xffffffffu, mx0, o));
        mx1 = fmaxf(mx1, __shfl_xor_sync(0xffffffffu, mx1, o));
    }

    float tlo0 = mx0 - 1.0f, tlo1 = mx1 - 1.0f;
    float dm = 0.96875f;   // tau_hi - tau_lo = 1 - (1/1024)^0.5 (row-independent)

    // f_lo
    float fl0 = 0.f, fl1 = 0.f;
#pragma unroll
    for (int j = 0; j < 32; j++) {
        float t = fmaxf(s0[j] - tlo0, 0.f); fl0 = fmaf(t, t, fl0);
        t = fmaxf(s1[j] - tlo1, 0.f);       fl1 = fmaf(t, t, fl1);
    }
#pragma unroll
    for (int o = 16; o > 0; o >>= 1) {
        fl0 += __shfl_xor_sync(0xffffffffu, fl0, o);
        fl1 += __shfl_xor_sync(0xffffffffu, fl1, o);
    }
    fl0 -= 1.0f; fl1 -= 1.0f;

    float tm0 = tlo0, tm1 = tlo1;
#pragma unroll 1
    for (int it = 0; it < BISECT_ITERS; it++) {
        dm *= 0.5f;
        tm0 = tlo0 + dm; tm1 = tlo1 + dm;
        float c0 = 0.f, c1 = 0.f;
#pragma unroll
        for (int j = 0; j < 32; j++) {
            float t = fmaxf(s0[j] - tm0, 0.f); c0 = fmaf(t, t, c0);
            t = fmaxf(s1[j] - tm1, 0.f);       c1 = fmaf(t, t, c1);
        }
#pragma unroll
        for (int o = 16; o > 0; o >>= 1) {
            c0 += __shfl_xor_sync(0xffffffffu, c0, o);
            c1 += __shfl_xor_sync(0xffffffffu, c1, o);
        }
        if ((c0 - 1.0f) * fl0 >= 0.f) tlo0 = tm0;
        if ((c1 - 1.0f) * fl1 >= 0.f) tlo1 = tm1;
    }

    // Analytic: on support S(tau), tau* = (s1 - sqrt(s1^2 - n*(s2-1))) / n
#pragma unroll 1
    for (int ps = 0; ps < SOLVE_ITERS; ps++) {
        float n0c = 0.f, sa1 = 0.f, sa2 = 0.f;
        float n1c = 0.f, sb1 = 0.f, sb2 = 0.f;
#pragma unroll
        for (int j = 0; j < 32; j++) {
            float a = s0[j];
            if (a > tm0) { n0c += 1.0f; sa1 += a; sa2 = fmaf(a, a, sa2); }
            float b = s1[j];
            if (b > tm1) { n1c += 1.0f; sb1 += b; sb2 = fmaf(b, b, sb2); }
        }
#pragma unroll
        for (int o = 16; o > 0; o >>= 1) {
            n0c += __shfl_xor_sync(0xffffffffu, n0c, o);
            sa1 += __shfl_xor_sync(0xffffffffu, sa1, o);
            sa2 += __shfl_xor_sync(0xffffffffu, sa2, o);
            n1c += __shfl_xor_sync(0xffffffffu, n1c, o);
            sb1 += __shfl_xor_sync(0xffffffffu, sb1, o);
            sb2 += __shfl_xor_sync(0xffffffffu, sb2, o);
        }
        float D0 = fmaxf(fmaf(sa1, sa1, -n0c * (sa2 - 1.0f)), 0.f);
        float D1 = fmaxf(fmaf(sb1, sb1, -n1c * (sb2 - 1.0f)), 0.f);
        tm0 = (sa1 - sqrtf(D0)) / n0c;
        tm1 = (sb1 - sqrtf(D1)) / n1c;
    }

    // final p + normalize
    float su0 = 0.f, su1 = 0.f;
#pragma unroll
    for (int j = 0; j < 32; j++) {
        float t = fmaxf(s0[j] - tm0, 0.f); s0[j] = t * t; su0 += s0[j];
        t = fmaxf(s1[j] - tm1, 0.f);       s1[j] = t * t; su1 += s1[j];
    }
#pragma unroll
    for (int o = 16; o > 0; o >>= 1) {
        su0 += __shfl_xor_sync(0xffffffffu, su0, o);
        su1 += __shfl_xor_sync(0xffffffffu, su1, o);
    }
    float inv0 = 1.0f / su0, inv1 = 1.0f / su1;

    float* ar0 = attn + ((size_t)bh * SEQ + rowbase + r0) * SEQ;
    float* ar1 = ar0 + SEQ;
#pragma unroll
    for (int c = 0; c < 16; c++) {
        ar0[c * 64 + l]      = s0[2 * c] * inv0;
        ar0[c * 64 + 32 + l] = s0[2 * c + 1] * inv0;
        ar1[c * 64 + l]      = s1[2 * c] * inv1;
        ar1[c * 64 + 32 + l] = s1[2 * c + 1] * inv1;
    }
}

// ---------------------------------------------------------------------------
// attn @ V per head: [1024x1024]@[1024x64]. BM=256, BN=64, BK=16,
// 256 threads, 8x8 microtile, 2-stage smem.
// ---------------------------------------------------------------------------
__global__ __launch_bounds__(256) void gemm_av(const float* __restrict__ attn)
{
    __shared__ float As[2][16][260];   // [k][m]
    __shared__ float Bs[2][16][68];    // [k][n]

    int tid = threadIdx.x;
    int tx = tid & 7;          // n: 8 * 8 = 64
    int ty = tid >> 3;         // m: 32 * 8 = 256
    int m0 = blockIdx.x * 256;
    int bh = blockIdx.y;

    const float* A = attn + (size_t)bh * SEQ * SEQ;
    const float* V = g_v + (size_t)bh * SEQ * DH;

    // A tile: 256 x 16 = 1024 f4 (4 f4/row), 4 per thread
    int ar[4], ac[4];
#pragma unroll
    for (int i = 0; i < 4; i++) {
        int idx = tid + i * 256;
        ar[i] = idx >> 2; ac[i] = idx & 3;
    }
    // B tile: 16 x 64 = 256 f4, 1 per thread
    int br = tid >> 4, bc = tid & 15;

    float4 ra[4], rb;
#pragma unroll
    for (int i = 0; i < 4; i++)
        ra[i] = *(const float4*)(A + (size_t)(m0 + ar[i]) * SEQ + ac[i] * 4);
    rb = *(const float4*)(V + (size_t)br * DH + bc * 4);

#pragma unroll
    for (int i = 0; i < 4; i++) {
        As[0][ac[i] * 4 + 0][ar[i]] = ra[i].x;
        As[0][ac[i] * 4 + 1][ar[i]] = ra[i].y;
        As[0][ac[i] * 4 + 2][ar[i]] = ra[i].z;
        As[0][ac[i] * 4 + 3][ar[i]] = ra[i].w;
    }
    *(float4*)&Bs[0][br][bc * 4] = rb;
    __syncthreads();

    float acc[8][8];
#pragma unroll
    for (int i = 0; i < 8; i++)
#pragma unroll
        for (int j = 0; j < 8; j++) acc[i][j] = 0.0f;

#pragma unroll 1
    for (int t = 0; t < 64; t++) {
        int buf = t & 1;
        if (t < 63) {
            int kn = (t + 1) * 16;
#pragma unroll
            for (int i = 0; i < 4; i++)
                ra[i] = *(const float4*)(A + (size_t)(m0 + ar[i]) * SEQ + kn + ac[i] * 4);
            rb = *(const float4*)(V + (size_t)(kn + br) * DH + bc * 4);
        }
#pragma unroll
        for (int k = 0; k < 16; k++) {
            float4 a0 = *(const float4*)&As[buf][k][ty * 8];
            float4 a1 = *(const float4*)&As[buf][k][ty * 8 + 4];
            float4 b0 = *(const float4*)&Bs[buf][k][tx * 8];
            float4 b1 = *(const float4*)&Bs[buf][k][tx * 8 + 4];
            float a[8] = {a0.x, a0.y, a0.z, a0.w, a1.x, a1.y, a1.z, a1.w};
            float b[8] = {b0.x, b0.y, b0.z, b0.w, b1.x, b1.y, b1.z, b1.w};
#pragma unroll
            for (int i = 0; i < 8; i++)
#pragma unroll
                for (int j = 0; j < 8; j++)
                    acc[i][j] = fmaf(a[i], b[j], acc[i][j]);
        }
        if (t < 63) {
            int nb = buf ^ 1;
#pragma unroll
            for (int i = 0; i < 4; i++) {
                As[nb][ac[i] * 4 + 0][ar[i]] = ra[i].x;
                As[nb][ac[i] * 4 + 1][ar[i]] = ra[i].y;
                As[nb][ac[i] * 4 + 2][ar[i]] = ra[i].z;
                As[nb][ac[i] * 4 + 3][ar[i]] = ra[i].w;
            }
            *(float4*)&Bs[nb][br][bc * 4] = rb;
            __syncthreads();
        }
    }

    int bidx = bh >> 4, h = bh & 15;
#pragma unroll
    for (int i = 0; i < 8; i++) {
        int m = m0 + ty * 8 + i;
        float* p = g_ctx + ((size_t)(bidx * SEQ + m)) * CH + h * DH + tx * 8;
        float4 v0 = {acc[i][0], acc[i][1], acc[i][2], acc[i][3]};
        float4 v1 = {acc[i][4], acc[i][5], acc[i][6], acc[i][7]};
        *(float4*)p = v0;
        *(float4*)(p + 4) = v1;
    }
}

// ---------------------------------------------------------------------------
extern "C" void kernel_launch(void* const* d_in, const int* in_sizes, int n_in,
                              void* d_out, int out_size)
{
    const float* x  = (const float*)d_in[0];
    const float* Wq = (const float*)d_in[1];
    const float* bq = (const float*)d_in[2];
    const float* Wk = (const float*)d_in[3];
    const float* bk = (const float*)d_in[4];
    const float* Wv = (const float*)d_in[5];
    const float* bv = (const float*)d_in[6];
    const float* Wo = (const float*)d_in[7];
    const float* bo = (const float*)d_in[8];

    float* out_ptr  = (float*)d_out;
    float* attn_ptr = out_ptr + OUT_ELEMS;

    dim3 gx(8, 32);     // 1024/128, 4096/128
    gemm_xw<<<gx, 256>>>(x, Wq, bq, nullptr, 0, 0);
    gemm_xw<<<gx, 256>>>(x, Wk, bk, nullptr, 0, 1);
    gemm_xw<<<gx, 256>>>(x, Wv, bv, nullptr, 0, 2);

    dim3 ge(32, BH);
    attn_entmax<<<ge, 512>>>(attn_ptr);

    dim3 ga(4, BH);     // 1024/256, 64
    gemm_av<<<ga, 256>>>(attn_ptr);

    gemm_xw<<<gx, 256>>>(nullptr, Wo, bo, out_ptr, 1, 3);
}

// round 4
// speedup vs baseline: 1.4777x; 1.4089x over previous
#include <cuda_runtime.h>
#include <cuda_bf16.h>
#include <cstdint>

#define BATCH 4
#define SEQ   1024
#define CH    1024
#define HEADS 16
#define DH    64
#define TOKENS (BATCH * SEQ)
#define BH (BATCH * HEADS)
#define OUT_ELEMS (TOKENS * CH)

#define BISECT_ITERS 12
#define SOLVE_ITERS 3
#define SCALE 0.0625f   // (1/sqrt(64)) * (alpha-1)

// fp32 scratch
__device__ float g_q[BH * SEQ * DH];
__device__ float g_k[BH * SEQ * DH];
__device__ float g_v[BH * SEQ * DH];
__device__ float g_ctx[TOKENS * CH];
// bf16 split scratch
__device__ __nv_bfloat16 g_xhi[TOKENS * CH];
__device__ __nv_bfloat16 g_xlo[TOKENS * CH];
__device__ __nv_bfloat16 g_wthi[4 * CH * CH];   // transposed weights [n][k]
__device__ __nv_bfloat16 g_wtlo[4 * CH * CH];
__device__ __nv_bfloat16 g_chi[TOKENS * CH];
__device__ __nv_bfloat16 g_clo[TOKENS * CH];

// ===================== PTX helpers =========================================
__device__ __forceinline__ uint32_t smem_u32(const void* p) {
    uint32_t a;
    asm("{ .reg .u64 t; cvta.to.shared.u64 t, %1; cvt.u32.u64 %0, t; }" : "=r"(a) : "l"(p));
    return a;
}
#define CP_ASYNC16(sa, g) \
    asm volatile("cp.async.cg.shared.global [%0], [%1], 16;" :: "r"(sa), "l"(g))
#define CP_COMMIT() asm volatile("cp.async.commit_group;" ::: "memory")
#define CP_WAIT0() asm volatile("cp.async.wait_group 0;" ::: "memory")
#define CP_WAIT1() asm volatile("cp.async.wait_group 1;" ::: "memory")
#define LDSM4(r0, r1, r2, r3, addr) \
    asm volatile("ldmatrix.sync.aligned.m8n8.x4.shared.b16 {%0,%1,%2,%3}, [%4];" \
        : "=r"(r0), "=r"(r1), "=r"(r2), "=r"(r3) : "r"(addr))
#define MMA16816(d, a, b0, b1) \
    asm volatile("mma.sync.aligned.m16n8k16.row.col.f32.bf16.bf16.f32 " \
        "{%0,%1,%2,%3}, {%4,%5,%6,%7}, {%8,%9}, {%0,%1,%2,%3};" \
        : "+f"((d)[0]), "+f"((d)[1]), "+f"((d)[2]), "+f"((d)[3]) \
        : "r"((a)[0]), "r"((a)[1]), "r"((a)[2]), "r"((a)[3]), "r"(b0), "r"(b1))

// ===================== convert kernels =====================================
__global__ __launch_bounds__(256) void split_convert(
    const float* __restrict__ in, __nv_bfloat16* __restrict__ hi,
    __nv_bfloat16* __restrict__ lo, int n4)
{
    int i = blockIdx.x * 256 + threadIdx.x;
    if (i >= n4) return;
    float4 v = ((const float4*)in)[i];
    union { ushort u[4]; uint2 q; } H, L;
    float a[4] = {v.x, v.y, v.z, v.w};
#pragma unroll
    for (int j = 0; j < 4; j++) {
        __nv_bfloat16 h = __float2bfloat16_rn(a[j]);
        __nv_bfloat16 l = __float2bfloat16_rn(a[j] - __bfloat162float(h));
        H.u[j] = __bfloat16_as_ushort(h);
        L.u[j] = __bfloat16_as_ushort(l);
    }
    ((uint2*)hi)[i] = H.q;
    ((uint2*)lo)[i] = L.q;
}

// transpose + split: out[n][k] = W[k][n]
__global__ __launch_bounds__(256) void wtrans_convert(
    const float* __restrict__ W, __nv_bfloat16* __restrict__ hi,
    __nv_bfloat16* __restrict__ lo)
{
    __shared__ float t[32][33];
    int tx = threadIdx.x, ty = threadIdx.y;
    int bx = blockIdx.x, by = blockIdx.y;
#pragma unroll
    for (int i = 0; i < 4; i++)
        t[ty + i * 8][tx] = W[(size_t)(by * 32 + ty + i * 8) * 1024 + bx * 32 + tx];
    __syncthreads();
#pragma unroll
    for (int i = 0; i < 4; i++) {
        float v = t[tx][ty + i * 8];
        __nv_bfloat16 h = __float2bfloat16_rn(v);
        __nv_bfloat16 l = __float2bfloat16_rn(v - __bfloat162float(h));
        size_t o = (size_t)(bx * 32 + ty + i * 8) * 1024 + by * 32 + tx;
        hi[o] = h;
        lo[o] = l;
    }
}

// ===================== split-bf16 mma.sync GEMM ============================
// D[4096,1024] = A @ B^T + bias.  A,B stored [rows][K=1024] bf16 hi/lo.
// 128x128 CTA tile, BK=32, 8 warps (2m x 4n), 3-stage cp.async pipeline.
// smem per stage: 4 tiles x (128x32 bf16 = 8KB) = 32KB; 3 stages = 96KB.
#define GSTAGE 32768
#define GSMEM (3 * GSTAGE)

__global__ __launch_bounds__(256) void gemm_mma(
    const __nv_bfloat16* __restrict__ Ah, const __nv_bfloat16* __restrict__ Al,
    const __nv_bfloat16* __restrict__ Bh, const __nv_bfloat16* __restrict__ Bl,
    const float* __restrict__ bias, float* __restrict__ dst, int reorder)
{
    extern __shared__ char sm[];
    uint32_t sb = smem_u32(sm);
    int tid = threadIdx.x, lane = tid & 31, wid = tid >> 5;
    int wm = wid >> 2, wn = wid & 3;
    int n0 = blockIdx.x * 128, m0 = blockIdx.y * 128;

    const __nv_bfloat16* gsrc[4] = {
        Ah + (size_t)m0 * 1024, Al + (size_t)m0 * 1024,
        Bh + (size_t)n0 * 1024, Bl + (size_t)n0 * 1024 };

    // load mapping: 512 16B-chunks per tile; thread does chunks tid, tid+256
    int l_row0 = tid >> 2,        l_c0 = tid & 3;
    int l_row1 = (tid + 256) >> 2, l_c1 = (tid + 256) & 3;

    auto load_stage = [&](int kt, int s) {
        uint32_t sbase = sb + s * GSTAGE;
#pragma unroll
        for (int t = 0; t < 4; t++) {
            const char* g0 = (const char*)(gsrc[t] + (size_t)l_row0 * 1024 + kt * 32) + l_c0 * 16;
            const char* g1 = (const char*)(gsrc[t] + (size_t)l_row1 * 1024 + kt * 32) + l_c1 * 16;
            uint32_t s0 = sbase + t * 8192 + l_row0 * 64 + ((l_c0 ^ (l_row0 & 3)) * 16);
            uint32_t s1 = sbase + t * 8192 + l_row1 * 64 + ((l_c1 ^ (l_row1 & 3)) * 16);
            CP_ASYNC16(s0, g0);
            CP_ASYNC16(s1, g1);
        }
        CP_COMMIT();
    };

    float acc[4][4][4];
#pragma unroll
    for (int a = 0; a < 4; a++)
#pragma unroll
        for (int b = 0; b < 4; b++)
#pragma unroll
            for (int c = 0; c < 4; c++) acc[a][b][c] = 0.0f;

    // ldmatrix lane mappings
    int arow = (lane & 7) | (((lane >> 3) & 1) << 3);  // 0..15
    int asel = lane >> 4;                              // k-chunk select
    int brow = (lane & 7) | ((lane >> 4) << 3);
    int bsel = (lane >> 3) & 1;

    load_stage(0, 0);
    load_stage(1, 1);

#pragma unroll 1
    for (int t = 0; t < 32; t++) {
        if (t >= 30) { CP_WAIT0(); } else { CP_WAIT1(); }
        __syncthreads();
        if (t + 2 < 32) load_stage(t + 2, (t + 2) % 3);

        uint32_t base = sb + (t % 3) * GSTAGE;
        uint32_t Ahb = base, Alb = base + 8192, Bhb = base + 16384, Blb = base + 24576;

#pragma unroll
        for (int ks = 0; ks < 2; ks++) {
            int akc = ks * 2 + asel;
            int bkc = ks * 2 + bsel;
            uint32_t ah[4][4], al[4][4], bh[2][4], bl[2][4];
#pragma unroll
            for (int mt = 0; mt < 4; mt++) {
                int row = wm * 64 + mt * 16 + arow;
                uint32_t off = row * 64 + ((akc ^ (row & 3)) * 16);
                LDSM4(ah[mt][0], ah[mt][1], ah[mt][2], ah[mt][3], Ahb + off);
            }
#pragma unroll
            for (int nt = 0; nt < 2; nt++) {
                int row = wn * 32 + nt * 16 + brow;
                uint32_t off = row * 64 + ((bkc ^ (row & 3)) * 16);
                LDSM4(bh[nt][0], bh[nt][1], bh[nt][2], bh[nt][3], Bhb + off);
            }
            // hh
#pragma unroll
            for (int mt = 0; mt < 4; mt++)
#pragma unroll
                for (int nt = 0; nt < 2; nt++) {
                    MMA16816(acc[mt][nt * 2 + 0], ah[mt], bh[nt][0], bh[nt][1]);
                    MMA16816(acc[mt][nt * 2 + 1], ah[mt], bh[nt][2], bh[nt][3]);
                }
            // hl
#pragma unroll
            for (int nt = 0; nt < 2; nt++) {
                int row = wn * 32 + nt * 16 + brow;
                uint32_t off = row * 64 + ((bkc ^ (row & 3)) * 16);
                LDSM4(bl[nt][0], bl[nt][1], bl[nt][2], bl[nt][3], Blb + off);
            }
#pragma unroll
            for (int mt = 0; mt < 4; mt++)
#pragma unroll
                for (int nt = 0; nt < 2; nt++) {
                    MMA16816(acc[mt][nt * 2 + 0], ah[mt], bl[nt][0], bl[nt][1]);
                    MMA16816(acc[mt][nt * 2 + 1], ah[mt], bl[nt][2], bl[nt][3]);
                }
            // lh
#pragma unroll
            for (int mt = 0; mt < 4; mt++) {
                int row = wm * 64 + mt * 16 + arow;
                uint32_t off = row * 64 + ((akc ^ (row & 3)) * 16);
                LDSM4(al[mt][0], al[mt][1], al[mt][2], al[mt][3], Alb + off);
            }
#pragma unroll
            for (int mt = 0; mt < 4; mt++)
#pragma unroll
                for (int nt = 0; nt < 2; nt++) {
                    MMA16816(acc[mt][nt * 2 + 0], al[mt], bh[nt][0], bh[nt][1]);
                    MMA16816(acc[mt][nt * 2 + 1], al[mt], bh[nt][2], bh[nt][3]);
                }
        }
        __syncthreads();
    }

    // epilogue
    int r = lane >> 2, c2 = (lane & 3) * 2;
#pragma unroll
    for (int mt = 0; mt < 4; mt++) {
        int mrow = m0 + wm * 64 + mt * 16 + r;
#pragma unroll
        for (int nt8 = 0; nt8 < 4; nt8++) {
            int col = n0 + wn * 32 + nt8 * 8 + c2;
            float b0 = bias[col], b1 = bias[col + 1];
            float2 v0 = {acc[mt][nt8][0] + b0, acc[mt][nt8][1] + b1};
            float2 v1 = {acc[mt][nt8][2] + b0, acc[mt][nt8][3] + b1};
            if (reorder) {
                int h = col >> 6, dh = col & 63;
                int bidx = mrow >> 10, ntok = mrow & 1023;
                float* p = dst + (((size_t)(bidx * HEADS + h)) * SEQ + ntok) * DH + dh;
                *(float2*)p = v0;
                *(float2*)(p + 8 * DH) = v1;
            } else {
                float* p = dst + (size_t)mrow * CH + col;
                *(float2*)p = v0;
                *(float2*)(p + 8 * CH) = v1;
            }
        }
    }
}

// ---------------------------------------------------------------------------
// Fused scores + entmax-1.5 (unchanged from R2)
// ---------------------------------------------------------------------------
__global__ __launch_bounds__(512) void attn_entmax(float* __restrict__ attn)
{
    __shared__ float Qs[32][68];
    __shared__ float Ks[64][68];

    int tid = threadIdx.x;
    int w = tid >> 5;
    int l = tid & 31;
    int bh = blockIdx.y;
    int rowbase = blockIdx.x * 32;
    int r0 = w * 2;

    const float* qbase = g_q + ((size_t)bh * SEQ + rowbase) * DH;
    const float* kbase = g_k + (size_t)bh * SEQ * DH;

    {
        int row = tid >> 4, c4 = tid & 15;
        float4 v = *(const float4*)(qbase + (size_t)row * DH + c4 * 4);
        *(float4*)&Qs[row][c4 * 4] = v;
    }

    int k_row0 = tid >> 4;
    int k_row1 = k_row0 + 32;
    int k_c4 = (tid & 15) * 4;

    float4 rk0 = *(const float4*)(kbase + (size_t)k_row0 * DH + k_c4);
    float4 rk1 = *(const float4*)(kbase + (size_t)k_row1 * DH + k_c4);

    float s0[32], s1[32];
    __syncthreads();

#pragma unroll
    for (int c = 0; c < 16; c++) {
        *(float4*)&Ks[k_row0][k_c4] = rk0;
        *(float4*)&Ks[k_row1][k_c4] = rk1;
        __syncthreads();
        if (c < 15) {
            const float* kn = kbase + (size_t)(c + 1) * 64 * DH;
            rk0 = *(const float4*)(kn + (size_t)k_row0 * DH + k_c4);
            rk1 = *(const float4*)(kn + (size_t)k_row1 * DH + k_c4);
        }
        float a00 = 0.f, a01 = 0.f, a10 = 0.f, a11 = 0.f;
#pragma unroll
        for (int d4 = 0; d4 < 16; d4++) {
            float4 k0 = *(const float4*)&Ks[l][d4 * 4];
            float4 k1 = *(const float4*)&Ks[l + 32][d4 * 4];
            float4 q0 = *(const float4*)&Qs[r0][d4 * 4];
            float4 q1 = *(const float4*)&Qs[r0 + 1][d4 * 4];
            a00 = fmaf(q0.x, k0.x, a00); a00 = fmaf(q0.y, k0.y, a00);
            a00 = fmaf(q0.z, k0.z, a00); a00 = fmaf(q0.w, k0.w, a00);
            a01 = fmaf(q0.x, k1.x, a01); a01 = fmaf(q0.y, k1.y, a01);
            a01 = fmaf(q0.z, k1.z, a01); a01 = fmaf(q0.w, k1.w, a01);
            a10 = fmaf(q1.x, k0.x, a10); a10 = fmaf(q1.y, k0.y, a10);
            a10 = fmaf(q1.z, k0.z, a10); a10 = fmaf(q1.w, k0.w, a10);
            a11 = fmaf(q1.x, k1.x, a11); a11 = fmaf(q1.y, k1.y, a11);
            a11 = fmaf(q1.z, k1.z, a11); a11 = fmaf(q1.w, k1.w, a11);
        }
        s0[2 * c] = a00; s0[2 * c + 1] = a01;
        s1[2 * c] = a10; s1[2 * c + 1] = a11;
        __syncthreads();
    }

#pragma unroll
    for (int j = 0; j < 32; j++) { s0[j] *= SCALE; s1[j] *= SCALE; }

    float mx0 = s0[0], mx1 = s1[0];
#pragma unroll
    for (int j = 1; j < 32; j++) { mx0 = fmaxf(mx0, s0[j]); mx1 = fmaxf(mx1, s1[j]); }
#pragma unroll
    for (int o = 16; o > 0; o >>= 1) {
        mx0 = fmaxf(mx0, __shfl_xor_sync(0xffffffffu, mx0, o));
        mx1 = fmaxf(mx1, __shfl_xor_sync(0xffffffffu, mx1, o));
    }

    float tlo0 = mx0 - 1.0f, tlo1 = mx1 - 1.0f;
    float dm = 0.96875f;

    float fl0 = 0.f, fl1 = 0.f;
#pragma unroll
    for (int j = 0; j < 32; j++) {
        float t = fmaxf(s0[j] - tlo0, 0.f); fl0 = fmaf(t, t, fl0);
        t = fmaxf(s1[j] - tlo1, 0.f);       fl1 = fmaf(t, t, fl1);
    }
#pragma unroll
    for (int o = 16; o > 0; o >>= 1) {
        fl0 += __shfl_xor_sync(0xffffffffu, fl0, o);
        fl1 += __shfl_xor_sync(0xffffffffu, fl1, o);
    }
    fl0 -= 1.0f; fl1 -= 1.0f;

    float tm0 = tlo0, tm1 = tlo1;
#pragma unroll 1
    for (int it = 0; it < BISECT_ITERS; it++) {
        dm *= 0.5f;
        tm0 = tlo0 + dm; tm1 = tlo1 + dm;
        float c0 = 0.f, c1 = 0.f;
#pragma unroll
        for (int j = 0; j < 32; j++) {
            float t = fmaxf(s0[j] - tm0, 0.f); c0 = fmaf(t, t, c0);
            t = fmaxf(s1[j] - tm1, 0.f);       c1 = fmaf(t, t, c1);
        }
#pragma unroll
        for (int o = 16; o > 0; o >>= 1) {
            c0 += __shfl_xor_sync(0xffffffffu, c0, o);
            c1 += __shfl_xor_sync(0xffffffffu, c1, o);
        }
        if ((c0 - 1.0f) * fl0 >= 0.f) tlo0 = tm0;
        if ((c1 - 1.0f) * fl1 >= 0.f) tlo1 = tm1;
    }

#pragma unroll 1
    for (int ps = 0; ps < SOLVE_ITERS; ps++) {
        float n0c = 0.f, sa1 = 0.f, sa2 = 0.f;
        float n1c = 0.f, sb1 = 0.f, sb2 = 0.f;
#pragma unroll
        for (int j = 0; j < 32; j++) {
            float a = s0[j];
            if (a > tm0) { n0c += 1.0f; sa1 += a; sa2 = fmaf(a, a, sa2); }
            float b = s1[j];
            if (b > tm1) { n1c += 1.0f; sb1 += b; sb2 = fmaf(b, b, sb2); }
        }
#pragma unroll
        for (int o = 16; o > 0; o >>= 1) {
            n0c += __shfl_xor_sync(0xffffffffu, n0c, o);
            sa1 += __shfl_xor_sync(0xffffffffu, sa1, o);
            sa2 += __shfl_xor_sync(0xffffffffu, sa2, o);
            n1c += __shfl_xor_sync(0xffffffffu, n1c, o);
            sb1 += __shfl_xor_sync(0xffffffffu, sb1, o);
            sb2 += __shfl_xor_sync(0xffffffffu, sb2, o);
        }
        float D0 = fmaxf(fmaf(sa1, sa1, -n0c * (sa2 - 1.0f)), 0.f);
        float D1 = fmaxf(fmaf(sb1, sb1, -n1c * (sb2 - 1.0f)), 0.f);
        tm0 = (sa1 - sqrtf(D0)) / n0c;
        tm1 = (sb1 - sqrtf(D1)) / n1c;
    }

    float su0 = 0.f, su1 = 0.f;
#pragma unroll
    for (int j = 0; j < 32; j++) {
        float t = fmaxf(s0[j] - tm0, 0.f); s0[j] = t * t; su0 += s0[j];
        t = fmaxf(s1[j] - tm1, 0.f);       s1[j] = t * t; su1 += s1[j];
    }
#pragma unroll
    for (int o = 16; o > 0; o >>= 1) {
        su0 += __shfl_xor_sync(0xffffffffu, su0, o);
        su1 += __shfl_xor_sync(0xffffffffu, su1, o);
    }
    float inv0 = 1.0f / su0, inv1 = 1.0f / su1;

    float* ar0 = attn + ((size_t)bh * SEQ + rowbase + r0) * SEQ;
    float* ar1 = ar0 + SEQ;
#pragma unroll
    for (int c = 0; c < 16; c++) {
        ar0[c * 64 + l]      = s0[2 * c] * inv0;
        ar0[c * 64 + 32 + l] = s0[2 * c + 1] * inv0;
        ar1[c * 64 + l]      = s1[2 * c] * inv1;
        ar1[c * 64 + 32 + l] = s1[2 * c + 1] * inv1;
    }
}

// ---------------------------------------------------------------------------
// attn @ V per head (unchanged): BM=256, BN=64, BK=16, fp32.
// ---------------------------------------------------------------------------
__global__ __launch_bounds__(256) void gemm_av(const float* __restrict__ attn)
{
    __shared__ float As[2][16][260];
    __shared__ float Bs[2][16][68];

    int tid = threadIdx.x;
    int tx = tid & 7;
    int ty = tid >> 3;
    int m0 = blockIdx.x * 256;
    int bh = blockIdx.y;

    const float* A = attn + (size_t)bh * SEQ * SEQ;
    const float* V = g_v + (size_t)bh * SEQ * DH;

    int ar[4], ac[4];
#pragma unroll
    for (int i = 0; i < 4; i++) {
        int idx = tid + i * 256;
        ar[i] = idx >> 2; ac[i] = idx & 3;
    }
    int br = tid >> 4, bc = tid & 15;

    float4 ra[4], rb;
#pragma unroll
    for (int i = 0; i < 4; i++)
        ra[i] = *(const float4*)(A + (size_t)(m0 + ar[i]) * SEQ + ac[i] * 4);
    rb = *(const float4*)(V + (size_t)br * DH + bc * 4);

#pragma unroll
    for (int i = 0; i < 4; i++) {
        As[0][ac[i] * 4 + 0][ar[i]] = ra[i].x;
        As[0][ac[i] * 4 + 1][ar[i]] = ra[i].y;
        As[0][ac[i] * 4 + 2][ar[i]] = ra[i].z;
        As[0][ac[i] * 4 + 3][ar[i]] = ra[i].w;
    }
    *(float4*)&Bs[0][br][bc * 4] = rb;
    __syncthreads();

    float acc[8][8];
#pragma unroll
    for (int i = 0; i < 8; i++)
#pragma unroll
        for (int j = 0; j < 8; j++) acc[i][j] = 0.0f;

#pragma unroll 1
    for (int t = 0; t < 64; t++) {
        int buf = t & 1;
        if (t < 63) {
            int kn = (t + 1) * 16;
#pragma unroll
            for (int i = 0; i < 4; i++)
                ra[i] = *(const float4*)(A + (size_t)(m0 + ar[i]) * SEQ + kn + ac[i] * 4);
            rb = *(const float4*)(V + (size_t)(kn + br) * DH + bc * 4);
        }
#pragma unroll
        for (int k = 0; k < 16; k++) {
            float4 a0 = *(const float4*)&As[buf][k][ty * 8];
            float4 a1 = *(const float4*)&As[buf][k][ty * 8 + 4];
            float4 b0 = *(const float4*)&Bs[buf][k][tx * 8];
            float4 b1 = *(const float4*)&Bs[buf][k][tx * 8 + 4];
            float a[8] = {a0.x, a0.y, a0.z, a0.w, a1.x, a1.y, a1.z, a1.w};
            float b[8] = {b0.x, b0.y, b0.z, b0.w, b1.x, b1.y, b1.z, b1.w};
#pragma unroll
            for (int i = 0; i < 8; i++)
#pragma unroll
                for (int j = 0; j < 8; j++)
                    acc[i][j] = fmaf(a[i], b[j], acc[i][j]);
        }
        if (t < 63) {
            int nb = buf ^ 1;
#pragma unroll
            for (int i = 0; i < 4; i++) {
                As[nb][ac[i] * 4 + 0][ar[i]] = ra[i].x;
                As[nb][ac[i] * 4 + 1][ar[i]] = ra[i].y;
                As[nb][ac[i] * 4 + 2][ar[i]] = ra[i].z;
                As[nb][ac[i] * 4 + 3][ar[i]] = ra[i].w;
            }
            *(float4*)&Bs[nb][br][bc * 4] = rb;
            __syncthreads();
        }
    }

    int bidx = bh >> 4, h = bh & 15;
#pragma unroll
    for (int i = 0; i < 8; i++) {
        int m = m0 + ty * 8 + i;
        float* p = g_ctx + ((size_t)(bidx * SEQ + m)) * CH + h * DH + tx * 8;
        float4 v0 = {acc[i][0], acc[i][1], acc[i][2], acc[i][3]};
        float4 v1 = {acc[i][4], acc[i][5], acc[i][6], acc[i][7]};
        *(float4*)p = v0;
        *(float4*)(p + 4) = v1;
    }
}

// ---------------------------------------------------------------------------
extern "C" void kernel_launch(void* const* d_in, const int* in_sizes, int n_in,
                              void* d_out, int out_size)
{
    const float* x  = (const float*)d_in[0];
    const float* Wq = (const float*)d_in[1];
    const float* bq = (const float*)d_in[2];
    const float* Wk = (const float*)d_in[3];
    const float* bk = (const float*)d_in[4];
    const float* Wv = (const float*)d_in[5];
    const float* bv = (const float*)d_in[6];
    const float* Wo = (const float*)d_in[7];
    const float* bo = (const float*)d_in[8];

    float* out_ptr  = (float*)d_out;
    float* attn_ptr = out_ptr + OUT_ELEMS;

    float *p_q, *p_k, *p_v, *p_ctx;
    __nv_bfloat16 *p_xhi, *p_xlo, *p_wthi, *p_wtlo, *p_chi, *p_clo;
    cudaGetSymbolAddress((void**)&p_q, g_q);
    cudaGetSymbolAddress((void**)&p_k, g_k);
    cudaGetSymbolAddress((void**)&p_v, g_v);
    cudaGetSymbolAddress((void**)&p_ctx, g_ctx);
    cudaGetSymbolAddress((void**)&p_xhi, g_xhi);
    cudaGetSymbolAddress((void**)&p_xlo, g_xlo);
    cudaGetSymbolAddress((void**)&p_wthi, g_wthi);
    cudaGetSymbolAddress((void**)&p_wtlo, g_wtlo);
    cudaGetSymbolAddress((void**)&p_chi, g_chi);
    cudaGetSymbolAddress((void**)&p_clo, g_clo);

    cudaFuncSetAttribute(gemm_mma, cudaFuncAttributeMaxDynamicSharedMemorySize, GSMEM);

    // converts
    split_convert<<<OUT_ELEMS / 4 / 256, 256>>>(x, p_xhi, p_xlo, OUT_ELEMS / 4);
    dim3 wt(32, 32), wb(32, 8);
    wtrans_convert<<<wt, wb>>>(Wq, p_wthi + 0 * 1048576, p_wtlo + 0 * 1048576);
    wtrans_convert<<<wt, wb>>>(Wk, p_wthi + 1 * 1048576, p_wtlo + 1 * 1048576);
    wtrans_convert<<<wt, wb>>>(Wv, p_wthi + 2 * 1048576, p_wtlo + 2 * 1048576);
    wtrans_convert<<<wt, wb>>>(Wo, p_wthi + 3 * 1048576, p_wtlo + 3 * 1048576);

    // QKV projections on tensor cores (head-reordered)
    dim3 gg(8, 32);
    gemm_mma<<<gg, 256, GSMEM>>>(p_xhi, p_xlo, p_wthi + 0 * 1048576, p_wtlo + 0 * 1048576, bq, p_q, 1);
    gemm_mma<<<gg, 256, GSMEM>>>(p_xhi, p_xlo, p_wthi + 1 * 1048576, p_wtlo + 1 * 1048576, bk, p_k, 1);
    gemm_mma<<<gg, 256, GSMEM>>>(p_xhi, p_xlo, p_wthi + 2 * 1048576, p_wtlo + 2 * 1048576, bv, p_v, 1);

    // scores + entmax
    dim3 ge(32, BH);
    attn_entmax<<<ge, 512>>>(attn_ptr);

    // attn @ V
    dim3 ga(4, BH);
    gemm_av<<<ga, 256>>>(attn_ptr);

    // output projection
    split_convert<<<OUT_ELEMS / 4 / 256, 256>>>(p_ctx, p_chi, p_clo, OUT_ELEMS / 4);
    gemm_mma<<<gg, 256, GSMEM>>>(p_chi, p_clo, p_wthi + 3 * 1048576, p_wtlo + 3 * 1048576, bo, out_ptr, 0);
}

// round 6
// speedup vs baseline: 1.6122x; 1.0910x over previous
#include <cuda_runtime.h>
#include <cuda_bf16.h>
#include <cstdint>

#define BATCH 4
#define SEQ   1024
#define CH    1024
#define HEADS 16
#define DH    64
#define TOKENS (BATCH * SEQ)
#define BH (BATCH * HEADS)
#define OUT_ELEMS (TOKENS * CH)

#define BISECT_ITERS 12
#define SOLVE_ITERS 3
#define SCALE 0.0625f   // (1/sqrt(64)) * (alpha-1)

// bf16 split scratch
__device__ __nv_bfloat16 g_xhi[TOKENS * CH];
__device__ __nv_bfloat16 g_xlo[TOKENS * CH];
__device__ __nv_bfloat16 g_wthi[4 * CH * CH];
__device__ __nv_bfloat16 g_wtlo[4 * CH * CH];
__device__ __nv_bfloat16 g_qhi[BH * SEQ * DH];
__device__ __nv_bfloat16 g_qlo[BH * SEQ * DH];
__device__ __nv_bfloat16 g_khi[BH * SEQ * DH];
__device__ __nv_bfloat16 g_klo[BH * SEQ * DH];
__device__ __nv_bfloat16 g_vthi[BH * DH * SEQ];   // transposed V: [bh][dh][tok]
__device__ __nv_bfloat16 g_vtlo[BH * DH * SEQ];
__device__ __nv_bfloat16 g_phi[(size_t)BH * SEQ * SEQ];  // attn split
__device__ __nv_bfloat16 g_plo[(size_t)BH * SEQ * SEQ];
__device__ __nv_bfloat16 g_chi[TOKENS * CH];
__device__ __nv_bfloat16 g_clo[TOKENS * CH];

// ===================== PTX helpers =========================================
__device__ __forceinline__ uint32_t smem_u32(const void* p) {
    uint32_t a;
    asm("{ .reg .u64 t; cvta.to.shared.u64 t, %1; cvt.u32.u64 %0, t; }" : "=r"(a) : "l"(p));
    return a;
}
#define CP_ASYNC16(sa, g) \
    asm volatile("cp.async.cg.shared.global [%0], [%1], 16;" :: "r"(sa), "l"(g))
#define CP_COMMIT() asm volatile("cp.async.commit_group;" ::: "memory")
#define CP_WAIT0() asm volatile("cp.async.wait_group 0;" ::: "memory")
#define CP_WAIT1() asm volatile("cp.async.wait_group 1;" ::: "memory")
#define LDSM4(r0, r1, r2, r3, addr) \
    asm volatile("ldmatrix.sync.aligned.m8n8.x4.shared.b16 {%0,%1,%2,%3}, [%4];" \
        : "=r"(r0), "=r"(r1), "=r"(r2), "=r"(r3) : "r"(addr))
#define MMA16816(d, a, b0, b1) \
    asm volatile("mma.sync.aligned.m16n8k16.row.col.f32.bf16.bf16.f32 " \
        "{%0,%1,%2,%3}, {%4,%5,%6,%7}, {%8,%9}, {%0,%1,%2,%3};" \
        : "+f"((d)[0]), "+f"((d)[1]), "+f"((d)[2]), "+f"((d)[3]) \
        : "r"((a)[0]), "r"((a)[1]), "r"((a)[2]), "r"((a)[3]), "r"(b0), "r"(b1))

__device__ __forceinline__ void split1(float v, __nv_bfloat16& h, __nv_bfloat16& l) {
    h = __float2bfloat16_rn(v);
    l = __float2bfloat16_rn(v - __bfloat162float(h));
}

// ===================== convert kernels =====================================
__global__ __launch_bounds__(256) void split_convert(
    const float* __restrict__ in, __nv_bfloat16* __restrict__ hi,
    __nv_bfloat16* __restrict__ lo, int n4)
{
    int i = blockIdx.x * 256 + threadIdx.x;
    if (i >= n4) return;
    float4 v = ((const float4*)in)[i];
    union { ushort u[4]; uint2 q; } H, L;
    float a[4] = {v.x, v.y, v.z, v.w};
#pragma unroll
    for (int j = 0; j < 4; j++) {
        __nv_bfloat16 h, l; split1(a[j], h, l);
        H.u[j] = __bfloat16_as_ushort(h);
        L.u[j] = __bfloat16_as_ushort(l);
    }
    ((uint2*)hi)[i] = H.q;
    ((uint2*)lo)[i] = L.q;
}

__global__ __launch_bounds__(256) void wtrans_convert(
    const float* __restrict__ W, __nv_bfloat16* __restrict__ hi,
    __nv_bfloat16* __restrict__ lo)
{
    __shared__ float t[32][33];
    int tx = threadIdx.x, ty = threadIdx.y;
    int bx = blockIdx.x, by = blockIdx.y;
#pragma unroll
    for (int i = 0; i < 4; i++)
        t[ty + i * 8][tx] = W[(size_t)(by * 32 + ty + i * 8) * 1024 + bx * 32 + tx];
    __syncthreads();
#pragma unroll
    for (int i = 0; i < 4; i++) {
        float v = t[tx][ty + i * 8];
        __nv_bfloat16 h, l; split1(v, h, l);
        size_t o = (size_t)(bx * 32 + ty + i * 8) * 1024 + by * 32 + tx;
        hi[o] = h;
        lo[o] = l;
    }
}

// ===================== split-bf16 mma.sync GEMM (projections) ==============
#define GSTAGE 32768
#define GSMEM (3 * GSTAGE)

__global__ __launch_bounds__(256) void gemm_mma(
    const __nv_bfloat16* __restrict__ Ah, const __nv_bfloat16* __restrict__ Al,
    const __nv_bfloat16* __restrict__ Bh, const __nv_bfloat16* __restrict__ Bl,
    const float* __restrict__ bias, float* __restrict__ dstf,
    __nv_bfloat16* __restrict__ dhi, __nv_bfloat16* __restrict__ dlo, int mode)
{
    extern __shared__ char sm[];
    uint32_t sb = smem_u32(sm);
    int tid = threadIdx.x, lane = tid & 31, wid = tid >> 5;
    int wm = wid >> 2, wn = wid & 3;
    int n0 = blockIdx.x * 128, m0 = blockIdx.y * 128;

    const __nv_bfloat16* gsrc[4] = {
        Ah + (size_t)m0 * 1024, Al + (size_t)m0 * 1024,
        Bh + (size_t)n0 * 1024, Bl + (size_t)n0 * 1024 };

    int l_row0 = tid >> 2,         l_c0 = tid & 3;
    int l_row1 = (tid + 256) >> 2, l_c1 = (tid + 256) & 3;

    auto load_stage = [&](int kt, int s) {
        uint32_t sbase = sb + s * GSTAGE;
#pragma unroll
        for (int t = 0; t < 4; t++) {
            const char* g0 = (const char*)(gsrc[t] + (size_t)l_row0 * 1024 + kt * 32) + l_c0 * 16;
            const char* g1 = (const char*)(gsrc[t] + (size_t)l_row1 * 1024 + kt * 32) + l_c1 * 16;
            uint32_t s0 = sbase + t * 8192 + l_row0 * 64 + ((l_c0 ^ (l_row0 & 3)) * 16);
            uint32_t s1 = sbase + t * 8192 + l_row1 * 64 + ((l_c1 ^ (l_row1 & 3)) * 16);
            CP_ASYNC16(s0, g0);
            CP_ASYNC16(s1, g1);
        }
        CP_COMMIT();
    };

    float acc[4][4][4];
#pragma unroll
    for (int a = 0; a < 4; a++)
#pragma unroll
        for (int b = 0; b < 4; b++)
#pragma unroll
            for (int c = 0; c < 4; c++) acc[a][b][c] = 0.0f;

    int arow = (lane & 7) | (((lane >> 3) & 1) << 3);
    int asel = lane >> 4;
    int brow = (lane & 7) | ((lane >> 4) << 3);
    int bsel = (lane >> 3) & 1;

    load_stage(0, 0);
    load_stage(1, 1);

#pragma unroll 1
    for (int t = 0; t < 32; t++) {
        if (t >= 30) { CP_WAIT0(); } else { CP_WAIT1(); }
        __syncthreads();
        if (t + 2 < 32) load_stage(t + 2, (t + 2) % 3);

        uint32_t base = sb + (t % 3) * GSTAGE;
        uint32_t Ahb = base, Alb = base + 8192, Bhb = base + 16384, Blb = base + 24576;

#pragma unroll
        for (int ks = 0; ks < 2; ks++) {
            int akc = ks * 2 + asel;
            int bkc = ks * 2 + bsel;
            uint32_t ah[4][4], al[4][4], bhf[2][4], blf[2][4];
#pragma unroll
            for (int mt = 0; mt < 4; mt++) {
                int row = wm * 64 + mt * 16 + arow;
                uint32_t off = row * 64 + ((akc ^ (row & 3)) * 16);
                LDSM4(ah[mt][0], ah[mt][1], ah[mt][2], ah[mt][3], Ahb + off);
            }
#pragma unroll
            for (int nt = 0; nt < 2; nt++) {
                int row = wn * 32 + nt * 16 + brow;
                uint32_t off = row * 64 + ((bkc ^ (row & 3)) * 16);
                LDSM4(bhf[nt][0], bhf[nt][1], bhf[nt][2], bhf[nt][3], Bhb + off);
            }
#pragma unroll
            for (int mt = 0; mt < 4; mt++)
#pragma unroll
                for (int nt = 0; nt < 2; nt++) {
                    MMA16816(acc[mt][nt * 2 + 0], ah[mt], bhf[nt][0], bhf[nt][1]);
                    MMA16816(acc[mt][nt * 2 + 1], ah[mt], bhf[nt][2], bhf[nt][3]);
                }
#pragma unroll
            for (int nt = 0; nt < 2; nt++) {
                int row = wn * 32 + nt * 16 + brow;
                uint32_t off = row * 64 + ((bkc ^ (row & 3)) * 16);
                LDSM4(blf[nt][0], blf[nt][1], blf[nt][2], blf[nt][3], Blb + off);
            }
#pragma unroll
            for (int mt = 0; mt < 4; mt++)
#pragma unroll
                for (int nt = 0; nt < 2; nt++) {
                    MMA16816(acc[mt][nt * 2 + 0], ah[mt], blf[nt][0], blf[nt][1]);
                    MMA16816(acc[mt][nt * 2 + 1], ah[mt], blf[nt][2], blf[nt][3]);
                }
#pragma unroll
            for (int mt = 0; mt < 4; mt++) {
                int row = wm * 64 + mt * 16 + arow;
                uint32_t off = row * 64 + ((akc ^ (row & 3)) * 16);
                LDSM4(al[mt][0], al[mt][1], al[mt][2], al[mt][3], Alb + off);
            }
#pragma unroll
            for (int mt = 0; mt < 4; mt++)
#pragma unroll
                for (int nt = 0; nt < 2; nt++) {
                    MMA16816(acc[mt][nt * 2 + 0], al[mt], bhf[nt][0], bhf[nt][1]);
                    MMA16816(acc[mt][nt * 2 + 1], al[mt], bhf[nt][2], bhf[nt][3]);
                }
        }
        __syncthreads();
    }

    // epilogue
    int r = lane >> 2, c2 = (lane & 3) * 2;
#pragma unroll
    for (int mt = 0; mt < 4; mt++) {
        int mrow = m0 + wm * 64 + mt * 16 + r;
        int bidx = mrow >> 10, ntok = mrow & 1023;
#pragma unroll
        for (int nt8 = 0; nt8 < 4; nt8++) {
            int col = n0 + wn * 32 + nt8 * 8 + c2;
            float b0 = bias[col], b1 = bias[col + 1];
            float v00 = acc[mt][nt8][0] + b0, v01 = acc[mt][nt8][1] + b1;
            float v10 = acc[mt][nt8][2] + b0, v11 = acc[mt][nt8][3] + b1;
            if (mode == 0) {
                int h = col >> 6, dh = col & 63;
                size_t base = ((size_t)(bidx * HEADS + h) * SEQ + ntok) * DH + dh;
                __nv_bfloat16 h0, l0, h1, l1;
                split1(v00, h0, l0); split1(v01, h1, l1);
                *(__nv_bfloat162*)(dhi + base) = {h0, h1};
                *(__nv_bfloat162*)(dlo + base) = {l0, l1};
                split1(v10, h0, l0); split1(v11, h1, l1);
                *(__nv_bfloat162*)(dhi + base + 8 * DH) = {h0, h1};
                *(__nv_bfloat162*)(dlo + base + 8 * DH) = {l0, l1};
            } else if (mode == 1) {
                int h = col >> 6, dh = col & 63;
                size_t vb = ((size_t)(bidx * HEADS + h) * DH + dh) * SEQ + ntok;
                __nv_bfloat16 hh, ll;
                split1(v00, hh, ll); dhi[vb] = hh; dlo[vb] = ll;
                split1(v01, hh, ll); dhi[vb + SEQ] = hh; dlo[vb + SEQ] = ll;
                split1(v10, hh, ll); dhi[vb + 8] = hh; dlo[vb + 8] = ll;
                split1(v11, hh, ll); dhi[vb + SEQ + 8] = hh; dlo[vb + SEQ + 8] = ll;
            } else {
                float* p = dstf + (size_t)mrow * CH + col;
                *(float2*)p = {v00, v01};
                *(float2*)(p + 8 * CH) = {v10, v11};
            }
        }
    }
}

// ===================== fused HMMA scores + entmax ==========================
#define EOFF_QH 0
#define EOFF_QL 4096
#define EOFF_K  8192
#define EOFF_RED 73728
#define EOFF_TAU 76800
#define ESMEM 76928

__global__ __launch_bounds__(512) void attn_entmax_mma(
    float* __restrict__ attn,
    const __nv_bfloat16* __restrict__ qhi, const __nv_bfloat16* __restrict__ qlo,
    const __nv_bfloat16* __restrict__ khi, const __nv_bfloat16* __restrict__ klo,
    __nv_bfloat16* __restrict__ phi, __nv_bfloat16* __restrict__ plo)
{
    extern __shared__ char sm[];
    uint32_t sb = smem_u32(sm);
    float* RED0 = (float*)(sm + EOFF_RED);
    float* RED1 = RED0 + 256;
    float* RED2 = RED1 + 256;
    float* TAU  = (float*)(sm + EOFF_TAU);

    int tid = threadIdx.x, lane = tid & 31, wid = tid >> 5;
    int wrow = wid >> 3, wcol = wid & 7;
    int bh = blockIdx.y;
    int R0 = blockIdx.x * 32;

    {   // Q: 512 chunks, 1/thread (joins group 0 commit below)
        int hl = tid >> 8;
        int row = (tid >> 3) & 31;
        int u = tid & 7;
        const __nv_bfloat16* src = (hl ? qlo : qhi) + ((size_t)bh * SEQ + R0 + row) * DH + u * 8;
        uint32_t d = sb + EOFF_QH + hl * 4096 + row * 128 + ((u ^ (row & 7)) * 16);
        CP_ASYNC16(d, src);
    }
    auto loadK = [&](int c, int s) {
        uint32_t base = sb + EOFF_K + s * 32768;
#pragma unroll
        for (int i = 0; i < 4; i++) {
            int idx = tid + i * 512;
            int hl = idx >> 10;
            int row = (idx >> 3) & 127;
            int u = idx & 7;
            const __nv_bfloat16* src = (hl ? klo : khi) + ((size_t)bh * SEQ + c * 128 + row) * DH + u * 8;
            uint32_t d = base + hl * 16384 + row * 128 + ((u ^ (row & 7)) * 16);
            CP_ASYNC16(d, src);
        }
        CP_COMMIT();
    };
    loadK(0, 0);
    loadK(1, 1);

    float acc[16][4];
#pragma unroll
    for (int t = 0; t < 16; t++)
#pragma unroll
        for (int e = 0; e < 4; e++) acc[t][e] = 0.0f;

    int arow_ = wrow * 16 + ((lane & 7) | (((lane >> 3) & 1) << 3));
    int asel = lane >> 4;
    int brow_ = (lane & 7) | ((lane >> 4) << 3);
    int bsel = (lane >> 3) & 1;

#pragma unroll 1
    for (int c = 0; c < 8; c++) {
        if (c >= 7) { CP_WAIT0(); } else { CP_WAIT1(); }   // FIX: last chunk must fully land
        __syncthreads();
        if (wcol == c) {
            uint32_t KHb = sb + EOFF_K + (c & 1) * 32768;
            uint32_t KLb = KHb + 16384;
            uint32_t QHb = sb + EOFF_QH, QLb = sb + EOFF_QL;
#pragma unroll
            for (int kc = 0; kc < 4; kc++) {
                uint32_t au = (uint32_t)(kc * 2 + asel);
                uint32_t aoff = arow_ * 128 + ((au ^ (arow_ & 7)) * 16);
                uint32_t ah[4], al[4];
                LDSM4(ah[0], ah[1], ah[2], ah[3], QHb + aoff);
                LDSM4(al[0], al[1], al[2], al[3], QLb + aoff);
#pragma unroll
                for (int nt = 0; nt < 8; nt++) {
                    int krow = nt * 16 + brow_;
                    uint32_t bu = (uint32_t)(kc * 2 + bsel);
                    uint32_t boff = krow * 128 + ((bu ^ (krow & 7)) * 16);
                    uint32_t bh4[4], bl4[4];
                    LDSM4(bh4[0], bh4[1], bh4[2], bh4[3], KHb + boff);
                    LDSM4(bl4[0], bl4[1], bl4[2], bl4[3], KLb + boff);
                    // 4-term: exact product (hh + hl + lh + ll)
                    MMA16816(acc[nt * 2 + 0], ah, bh4[0], bh4[1]);
                    MMA16816(acc[nt * 2 + 1], ah, bh4[2], bh4[3]);
                    MMA16816(acc[nt * 2 + 0], ah, bl4[0], bl4[1]);
                    MMA16816(acc[nt * 2 + 1], ah, bl4[2], bl4[3]);
                    MMA16816(acc[nt * 2 + 0], al, bh4[0], bh4[1]);
                    MMA16816(acc[nt * 2 + 1], al, bh4[2], bh4[3]);
                    MMA16816(acc[nt * 2 + 0], al, bl4[0], bl4[1]);
                    MMA16816(acc[nt * 2 + 1], al, bl4[2], bl4[3]);
                }
            }
        }
        __syncthreads();
        if (c + 2 < 8) loadK(c + 2, c & 1);
    }

    // --- entmax in HMMA layout ---
    int r0 = wrow * 16 + (lane >> 2);
    int r1 = r0 + 8;

#pragma unroll
    for (int t = 0; t < 16; t++)
#pragma unroll
        for (int e = 0; e < 4; e++) acc[t][e] *= SCALE;

    float tlo = 0.f, fl = 0.f, dm = 0.f, tm = 0.f;

    // Phase A: row max
    {
        float mA = -1e30f, mB = -1e30f;
#pragma unroll
        for (int t = 0; t < 16; t++) {
            mA = fmaxf(mA, fmaxf(acc[t][0], acc[t][1]));
            mB = fmaxf(mB, fmaxf(acc[t][2], acc[t][3]));
        }
        mA = fmaxf(mA, __shfl_xor_sync(0xffffffffu, mA, 1));
        mA = fmaxf(mA, __shfl_xor_sync(0xffffffffu, mA, 2));
        mB = fmaxf(mB, __shfl_xor_sync(0xffffffffu, mB, 1));
        mB = fmaxf(mB, __shfl_xor_sync(0xffffffffu, mB, 2));
        if ((lane & 3) == 0) { RED0[r0 * 8 + wcol] = mA; RED0[r1 * 8 + wcol] = mB; }
    }
    __syncthreads();
    if (tid < 32) {
        float mx = -1e30f;
#pragma unroll
        for (int j = 0; j < 8; j++) mx = fmaxf(mx, RED0[tid * 8 + j]);
        tlo = mx - 1.0f;
        TAU[tid] = tlo;
    }
    __syncthreads();

    // Phase B: f_lo
    {
        float tA = TAU[r0], tB = TAU[r1];
        float c0 = 0.f, c1 = 0.f, c2 = 0.f, c3 = 0.f;
#pragma unroll
        for (int t = 0; t < 16; t++) {
            float u;
            u = fmaxf(acc[t][0] - tA, 0.f); c0 = fmaf(u, u, c0);
            u = fmaxf(acc[t][1] - tA, 0.f); c1 = fmaf(u, u, c1);
            u = fmaxf(acc[t][2] - tB, 0.f); c2 = fmaf(u, u, c2);
            u = fmaxf(acc[t][3] - tB, 0.f); c3 = fmaf(u, u, c3);
        }
        float vA = c0 + c1, vB = c2 + c3;
        vA += __shfl_xor_sync(0xffffffffu, vA, 1);
        vA += __shfl_xor_sync(0xffffffffu, vA, 2);
        vB += __shfl_xor_sync(0xffffffffu, vB, 1);
        vB += __shfl_xor_sync(0xffffffffu, vB, 2);
        if ((lane & 3) == 0) { RED0[r0 * 8 + wcol] = vA; RED0[r1 * 8 + wcol] = vB; }
    }
    __syncthreads();
    if (tid < 32) {
        float s = 0.f;
#pragma unroll
        for (int j = 0; j < 8; j++) s += RED0[tid * 8 + j];
        fl = s - 1.0f;
        dm = 0.484375f;
        tm = tlo + dm;
        TAU[tid] = tm;
    }
    __syncthreads();

    // Phase C: bisection
#pragma unroll 1
    for (int it = 0; it < BISECT_ITERS; it++) {
        float tA = TAU[r0], tB = TAU[r1];
        float c0 = 0.f, c1 = 0.f, c2 = 0.f, c3 = 0.f;
#pragma unroll
        for (int t = 0; t < 16; t++) {
            float u;
            u = fmaxf(acc[t][0] - tA, 0.f); c0 = fmaf(u, u, c0);
            u = fmaxf(acc[t][1] - tA, 0.f); c1 = fmaf(u, u, c1);
            u = fmaxf(acc[t][2] - tB, 0.f); c2 = fmaf(u, u, c2);
            u = fmaxf(acc[t][3] - tB, 0.f); c3 = fmaf(u, u, c3);
        }
        float vA = c0 + c1, vB = c2 + c3;
        vA += __shfl_xor_sync(0xffffffffu, vA, 1);
        vA += __shfl_xor_sync(0xffffffffu, vA, 2);
        vB += __shfl_xor_sync(0xffffffffu, vB, 1);
        vB += __shfl_xor_sync(0xffffffffu, vB, 2);
        if ((lane & 3) == 0) { RED0[r0 * 8 + wcol] = vA; RED0[r1 * 8 + wcol] = vB; }
        __syncthreads();
        if (tid < 32) {
            float s = 0.f;
#pragma unroll
            for (int j = 0; j < 8; j++) s += RED0[tid * 8 + j];
            float fm = s - 1.0f;
            if (fm * fl >= 0.f) tlo = tm;
            if (it < BISECT_ITERS - 1) {
                dm *= 0.5f;
                tm = tlo + dm;
                TAU[tid] = tm;
            }
        }
        __syncthreads();
    }

    // Phase D: analytic support-fixpoint solves
#pragma unroll 1
    for (int ps = 0; ps < SOLVE_ITERS; ps++) {
        float tA = TAU[r0], tB = TAU[r1];
        float nA = 0.f, s1A = 0.f, s2A = 0.f;
        float nB = 0.f, s1B = 0.f, s2B = 0.f;
#pragma unroll
        for (int t = 0; t < 16; t++) {
#pragma unroll
            for (int e = 0; e < 2; e++) {
                float a = acc[t][e];
                if (a > tA) { nA += 1.f; s1A += a; s2A = fmaf(a, a, s2A); }
                float b = acc[t][e + 2];
                if (b > tB) { nB += 1.f; s1B += b; s2B = fmaf(b, b, s2B); }
            }
        }
#pragma unroll
        for (int o = 1; o <= 2; o <<= 1) {
            nA += __shfl_xor_sync(0xffffffffu, nA, o);
            s1A += __shfl_xor_sync(0xffffffffu, s1A, o);
            s2A += __shfl_xor_sync(0xffffffffu, s2A, o);
            nB += __shfl_xor_sync(0xffffffffu, nB, o);
            s1B += __shfl_xor_sync(0xffffffffu, s1B, o);
            s2B += __shfl_xor_sync(0xffffffffu, s2B, o);
        }
        if ((lane & 3) == 0) {
            RED0[r0 * 8 + wcol] = nA;  RED0[r1 * 8 + wcol] = nB;
            RED1[r0 * 8 + wcol] = s1A; RED1[r1 * 8 + wcol] = s1B;
            RED2[r0 * 8 + wcol] = s2A; RED2[r1 * 8 + wcol] = s2B;
        }
        __syncthreads();
        if (tid < 32) {
            float n = 0.f, s1 = 0.f, s2 = 0.f;
#pragma unroll
            for (int j = 0; j < 8; j++) {
                n += RED0[tid * 8 + j];
                s1 += RED1[tid * 8 + j];
                s2 += RED2[tid * 8 + j];
            }
            float D = fmaxf(fmaf(s1, s1, -n * (s2 - 1.0f)), 0.f);
            TAU[tid] = (s1 - sqrtf(D)) / n;
        }
        __syncthreads();
    }

    // Phase E: final p + normalize + write
    {
        float tA = TAU[r0], tB = TAU[r1];
        float c0 = 0.f, c1 = 0.f, c2 = 0.f, c3 = 0.f;
#pragma unroll
        for (int t = 0; t < 16; t++) {
            float u;
            u = fmaxf(acc[t][0] - tA, 0.f); acc[t][0] = u * u; c0 += acc[t][0];
            u = fmaxf(acc[t][1] - tA, 0.f); acc[t][1] = u * u; c1 += acc[t][1];
            u = fmaxf(acc[t][2] - tB, 0.f); acc[t][2] = u * u; c2 += acc[t][2];
            u = fmaxf(acc[t][3] - tB, 0.f); acc[t][3] = u * u; c3 += acc[t][3];
        }
        float vA = c0 + c1, vB = c2 + c3;
        vA += __shfl_xor_sync(0xffffffffu, vA, 1);
        vA += __shfl_xor_sync(0xffffffffu, vA, 2);
        vB += __shfl_xor_sync(0xffffffffu, vB, 1);
        vB += __shfl_xor_sync(0xffffffffu, vB, 2);
        if ((lane & 3) == 0) { RED0[r0 * 8 + wcol] = vA; RED0[r1 * 8 + wcol] = vB; }
    }
    __syncthreads();
    if (tid < 32) {
        float s = 0.f;
#pragma unroll
        for (int j = 0; j < 8; j++) s += RED0[tid * 8 + j];
        TAU[tid] = 1.0f / s;
    }
    __syncthreads();
    {
        float ivA = TAU[r0], ivB = TAU[r1];
        size_t rb0 = ((size_t)bh * SEQ + R0 + r0) * SEQ + wcol * 128 + (lane & 3) * 2;
        size_t rb1 = ((size_t)bh * SEQ + R0 + r1) * SEQ + wcol * 128 + (lane & 3) * 2;
#pragma unroll
        for (int t = 0; t < 16; t++) {
            float p0 = acc[t][0] * ivA, p1 = acc[t][1] * ivA;
            float p2 = acc[t][2] * ivB, p3 = acc[t][3] * ivB;
            *(float2*)(attn + rb0 + t * 8) = {p0, p1};
            *(float2*)(attn + rb1 + t * 8) = {p2, p3};
            __nv_bfloat16 h0, l0, h1, l1;
            split1(p0, h0, l0); split1(p1, h1, l1);
            *(__nv_bfloat162*)(phi + rb0 + t * 8) = {h0, h1};
            *(__nv_bfloat162*)(plo + rb0 + t * 8) = {l0, l1};
            split1(p2, h0, l0); split1(p3, h1, l1);
            *(__nv_bfloat162*)(phi + rb1 + t * 8) = {h0, h1};
            *(__nv_bfloat162*)(plo + rb1 + t * 8) = {l0, l1};
        }
    }
}

// ===================== attn @ V via HMMA (split-bf16) ======================
#define VSTAGE 24576
#define VSMEM (3 * VSTAGE)

__global__ __launch_bounds__(256) void gemm_av_mma(
    const __nv_bfloat16* __restrict__ Ph, const __nv_bfloat16* __restrict__ Pl,
    const __nv_bfloat16* __restrict__ Vh, const __nv_bfloat16* __restrict__ Vl,
    __nv_bfloat16* __restrict__ chi, __nv_bfloat16* __restrict__ clo)
{
    extern __shared__ char sm[];
    uint32_t sb = smem_u32(sm);
    int tid = threadIdx.x, lane = tid & 31, wid = tid >> 5;
    int wm = wid >> 1, wn = wid & 1;
    int m0 = blockIdx.x * 128;
    int bh = blockIdx.y;

    const __nv_bfloat16* pa[2] = { Ph + ((size_t)bh * SEQ + m0) * SEQ,
                                   Pl + ((size_t)bh * SEQ + m0) * SEQ };
    const __nv_bfloat16* pb[2] = { Vh + (size_t)bh * DH * SEQ,
                                   Vl + (size_t)bh * DH * SEQ };

    auto load_stage = [&](int kt, int s) {
        uint32_t base = sb + s * VSTAGE;
#pragma unroll
        for (int i = 0; i < 4; i++) {
            int idx = tid + i * 256;
            int hl = idx >> 9;
            int row = (idx >> 2) & 127;
            int u = idx & 3;
            const __nv_bfloat16* g = pa[hl] + (size_t)row * SEQ + kt * 32 + u * 8;
            uint32_t d = base + hl * 8192 + row * 64 + ((u ^ (row & 3)) * 16);
            CP_ASYNC16(d, g);
        }
#pragma unroll
        for (int i = 0; i < 2; i++) {
            int idx = tid + i * 256;
            int hl = idx >> 8;
            int row = (idx >> 2) & 63;
            int u = idx & 3;
            const __nv_bfloat16* g = pb[hl] + (size_t)row * SEQ + kt * 32 + u * 8;
            uint32_t d = base + 16384 + hl * 4096 + row * 64 + ((u ^ (row & 3)) * 16);
            CP_ASYNC16(d, g);
        }
        CP_COMMIT();
    };

    float acc[2][4][4];
#pragma unroll
    for (int a = 0; a < 2; a++)
#pragma unroll
        for (int b = 0; b < 4; b++)
#pragma unroll
            for (int c = 0; c < 4; c++) acc[a][b][c] = 0.0f;

    int arow = (lane & 7) | (((lane >> 3) & 1) << 3);
    int asel = lane >> 4;
    int brow = (lane & 7) | ((lane >> 4) << 3);
    int bsel = (lane >> 3) & 1;

    load_stage(0, 0);
    load_stage(1, 1);

#pragma unroll 1
    for (int t = 0; t < 32; t++) {
        if (t >= 30) { CP_WAIT0(); } else { CP_WAIT1(); }
        __syncthreads();
        if (t + 2 < 32) load_stage(t + 2, (t + 2) % 3);

        uint32_t base = sb + (t % 3) * VSTAGE;
        uint32_t Ahb = base, Alb = base + 8192, Bhb = base + 16384, Blb = base + 20480;

#pragma unroll
        for (int ks = 0; ks < 2; ks++) {
            int akc = ks * 2 + asel;
            int bkc = ks * 2 + bsel;
            uint32_t ah[2][4], al[2][4], bh4[2][4], bl4[2][4];
#pragma unroll
            for (int mt = 0; mt < 2; mt++) {
                int row = wm * 32 + mt * 16 + arow;
                uint32_t off = row * 64 + ((akc ^ (row & 3)) * 16);
                LDSM4(ah[mt][0], ah[mt][1], ah[mt][2], ah[mt][3], Ahb + off);
                LDSM4(al[mt][0], al[mt][1], al[mt][2], al[mt][3], Alb + off);
            }
#pragma unroll
            for (int nt = 0; nt < 2; nt++) {
                int row = wn * 32 + nt * 16 + brow;
                uint32_t off = row * 64 + ((bkc ^ (row & 3)) * 16);
                LDSM4(bh4[nt][0], bh4[nt][1], bh4[nt][2], bh4[nt][3], Bhb + off);
                LDSM4(bl4[nt][0], bl4[nt][1], bl4[nt][2], bl4[nt][3], Blb + off);
            }
#pragma unroll
            for (int mt = 0; mt < 2; mt++)
#pragma unroll
                for (int nt = 0; nt < 2; nt++) {
                    MMA16816(acc[mt][nt * 2 + 0], ah[mt], bh4[nt][0], bh4[nt][1]);
                    MMA16816(acc[mt][nt * 2 + 1], ah[mt], bh4[nt][2], bh4[nt][3]);
                    MMA16816(acc[mt][nt * 2 + 0], ah[mt], bl4[nt][0], bl4[nt][1]);
                    MMA16816(acc[mt][nt * 2 + 1], ah[mt], bl4[nt][2], bl4[nt][3]);
                    MMA16816(acc[mt][nt * 2 + 0], al[mt], bh4[nt][0], bh4[nt][1]);
                    MMA16816(acc[mt][nt * 2 + 1], al[mt], bh4[nt][2], bh4[nt][3]);
                }
        }
        __syncthreads();
    }

    // epilogue: write ctx split [tok][1024]
    int r = lane >> 2, c2 = (lane & 3) * 2;
    int bidx = bh >> 4, h = bh & 15;
#pragma unroll
    for (int mt = 0; mt < 2; mt++) {
        int mrow = m0 + wm * 32 + mt * 16 + r;
        size_t tok0 = (size_t)(bidx * SEQ + mrow) * CH;
        size_t tok1 = (size_t)(bidx * SEQ + mrow + 8) * CH;
#pragma unroll
        for (int nt8 = 0; nt8 < 4; nt8++) {
            int col = h * DH + wn * 32 + nt8 * 8 + c2;
            __nv_bfloat16 h0, l0, h1, l1;
            split1(acc[mt][nt8][0], h0, l0); split1(acc[mt][nt8][1], h1, l1);
            *(__nv_bfloat162*)(chi + tok0 + col) = {h0, h1};
            *(__nv_bfloat162*)(clo + tok0 + col) = {l0, l1};
            split1(acc[mt][nt8][2], h0, l0); split1(acc[mt][nt8][3], h1, l1);
            *(__nv_bfloat162*)(chi + tok1 + col) = {h0, h1};
            *(__nv_bfloat162*)(clo + tok1 + col) = {l0, l1};
        }
    }
}

// ---------------------------------------------------------------------------
extern "C" void kernel_launch(void* const* d_in, const int* in_sizes, int n_in,
                              void* d_out, int out_size)
{
    const float* x  = (const float*)d_in[0];
    const float* Wq = (const float*)d_in[1];
    const float* bq = (const float*)d_in[2];
    const float* Wk = (const float*)d_in[3];
    const float* bk = (const float*)d_in[4];
    const float* Wv = (const float*)d_in[5];
    const float* bv = (const float*)d_in[6];
    const float* Wo = (const float*)d_in[7];
    const float* bo = (const float*)d_in[8];

    float* out_ptr  = (float*)d_out;
    float* attn_ptr = out_ptr + OUT_ELEMS;

    __nv_bfloat16 *p_xhi, *p_xlo, *p_wthi, *p_wtlo;
    __nv_bfloat16 *p_qhi, *p_qlo, *p_khi, *p_klo, *p_vthi, *p_vtlo;
    __nv_bfloat16 *p_phi, *p_plo, *p_chi, *p_clo;
    cudaGetSymbolAddress((void**)&p_xhi, g_xhi);
    cudaGetSymbolAddress((void**)&p_xlo, g_xlo);
    cudaGetSymbolAddress((void**)&p_wthi, g_wthi);
    cudaGetSymbolAddress((void**)&p_wtlo, g_wtlo);
    cudaGetSymbolAddress((void**)&p_qhi, g_qhi);
    cudaGetSymbolAddress((void**)&p_qlo, g_qlo);
    cudaGetSymbolAddress((void**)&p_khi, g_khi);
    cudaGetSymbolAddress((void**)&p_klo, g_klo);
    cudaGetSymbolAddress((void**)&p_vthi, g_vthi);
    cudaGetSymbolAddress((void**)&p_vtlo, g_vtlo);
    cudaGetSymbolAddress((void**)&p_phi, g_phi);
    cudaGetSymbolAddress((void**)&p_plo, g_plo);
    cudaGetSymbolAddress((void**)&p_chi, g_chi);
    cudaGetSymbolAddress((void**)&p_clo, g_clo);

    cudaFuncSetAttribute(gemm_mma, cudaFuncAttributeMaxDynamicSharedMemorySize, GSMEM);
    cudaFuncSetAttribute(attn_entmax_mma, cudaFuncAttributeMaxDynamicSharedMemorySize, ESMEM);
    cudaFuncSetAttribute(gemm_av_mma, cudaFuncAttributeMaxDynamicSharedMemorySize, VSMEM);

    split_convert<<<OUT_ELEMS / 4 / 256, 256>>>(x, p_xhi, p_xlo, OUT_ELEMS / 4);
    dim3 wt(32, 32), wb(32, 8);
    wtrans_convert<<<wt, wb>>>(Wq, p_wthi + 0 * 1048576, p_wtlo + 0 * 1048576);
    wtrans_convert<<<wt, wb>>>(Wk, p_wthi + 1 * 1048576, p_wtlo + 1 * 1048576);
    wtrans_convert<<<wt, wb>>>(Wv, p_wthi + 2 * 1048576, p_wtlo + 2 * 1048576);
    wtrans_convert<<<wt, wb>>>(Wo, p_wthi + 3 * 1048576, p_wtlo + 3 * 1048576);

    dim3 gg(8, 32);
    gemm_mma<<<gg, 256, GSMEM>>>(p_xhi, p_xlo, p_wthi + 0 * 1048576, p_wtlo + 0 * 1048576,
                                 bq, nullptr, p_qhi, p_qlo, 0);
    gemm_mma<<<gg, 256, GSMEM>>>(p_xhi, p_xlo, p_wthi + 1 * 1048576, p_wtlo + 1 * 1048576,
                                 bk, nullptr, p_khi, p_klo, 0);
    gemm_mma<<<gg, 256, GSMEM>>>(p_xhi, p_xlo, p_wthi + 2 * 1048576, p_wtlo + 2 * 1048576,
                                 bv, nullptr, p_vthi, p_vtlo, 1);

    dim3 ge(32, BH);
    attn_entmax_mma<<<ge, 512, ESMEM>>>(attn_ptr, p_qhi, p_qlo, p_khi, p_klo, p_phi, p_plo);

    dim3 ga(8, BH);
    gemm_av_mma<<<ga, 256, VSMEM>>>(p_phi, p_plo, p_vthi, p_vtlo, p_chi, p_clo);

    gemm_mma<<<gg, 256, GSMEM>>>(p_chi, p_clo, p_wthi + 3 * 1048576, p_wtlo + 3 * 1048576,
                                 bo, out_ptr, nullptr, nullptr, 2);
}